// round 8
// baseline (speedup 1.0000x reference)
#include <cuda_runtime.h>

#define BB 8
#define NN 1024
#define KK 20
#define CAT 512
#define O5 1024

typedef unsigned long long ull;

__device__ __forceinline__ ull ffma2(ull a, ull b, ull c) {
    ull d;
    asm("fma.rn.f32x2 %0, %1, %2, %3;" : "=l"(d) : "l"(a), "l"(b), "l"(c));
    return d;
}
__device__ __forceinline__ ull bcast2(float v) {
    ull d;
    asm("mov.b64 %0, {%1, %1};" : "=l"(d) : "f"(v));
    return d;
}
__device__ __forceinline__ void unpack2(ull p, float& lo, float& hi) {
    asm("mov.b64 {%0, %1}, %2;" : "=f"(lo), "=f"(hi) : "l"(p));
}

// -------- static device workspaces --------
__device__ float g_f0[BB * NN * 4];
__device__ float g_cat[BB * NN * CAT];
__device__ float g_xx[BB * NN];
__device__ float g_nd[BB * NN * NN];
__device__ int   g_idx[BB * NN * KK];
__device__ float g_v[BB * NN * 256];
__device__ float g_u[BB * NN * 256];
__device__ float g_wa[64 * 1024];
__device__ float g_wu[64 * 1024];
__device__ float g_maxv[BB * NN * 256];
__device__ float g_minv[BB * NN * 256];
__device__ float g_sum[O5];
__device__ float g_sq[O5];
__device__ float g_pmax[BB * O5 * 8];
__device__ float g_pmin[BB * O5 * 8];
__device__ float g_scale[256];
__device__ float g_bias[256];
__device__ int   g_cnt;

__device__ __forceinline__ const float* featPtr(int src, int off) {
    return src ? (g_cat + off) : g_f0;
}

// -------- fused prep: transpose x + xx(layer1) + ALL W splits + zero stats --------
__global__ void prep0(const float* __restrict__ x,
                      const float* __restrict__ W1, const float* __restrict__ W2,
                      const float* __restrict__ W3, const float* __restrict__ W4) {
    int bx = blockIdx.x;
    if (bx < 32) {
        int t = bx * 256 + threadIdx.x;
        int b = t / NN, n = t % NN;
        float x0 = x[(b * 3 + 0) * NN + n];
        float x1 = x[(b * 3 + 1) * NN + n];
        float x2 = x[(b * 3 + 2) * NN + n];
        float* d = g_f0 + (size_t)t * 4;
        d[0] = x0; d[1] = x1; d[2] = x2; d[3] = 0.f;
        float a = fmaf(x0, x0, 0.f);
        a = fmaf(x1, x1, a);
        a = fmaf(x2, x2, a);
        g_xx[t] = a;
    } else if (bx == 32) {
        for (int t = threadIdx.x; t < O5; t += 256) { g_sum[t] = 0.f; g_sq[t] = 0.f; }
    } else {
        int t = (bx - 33) * 256 + threadIdx.x;
        const float* W; int C, O, woff, local;
        if (t < 192)        { W = W1; C = 3;   O = 64;  woff = 0;     local = t; }
        else if (t < 4288)  { W = W2; C = 64;  O = 64;  woff = 256;   local = t - 192; }
        else if (t < 12480) { W = W3; C = 64;  O = 128; woff = 4608;  local = t - 4288; }
        else if (t < 45248) { W = W4; C = 128; O = 256; woff = 12800; local = t - 12480; }
        else return;
        int c = local / O, o = local % O;
        float wa = W[o * (2 * C) + c];
        float wb = W[o * (2 * C) + C + c];
        g_wa[woff + c * O + o] = wa;
        g_wu[woff + c * O + o] = wb - wa;
    }
}

// -------- neg pairwise distance Gram GEMM: symmetric, 128x128 tile, 8x8, f32x2 --------
__global__ __launch_bounds__(256, 2) void kd_kernel(int src, int off, int stride, int C) {
    __shared__ __align__(16) float Ad[16 * 260];
    __shared__ __align__(16) float Bs_[16 * 132];
    int b = blockIdx.z;
    int bi = 0, rem = blockIdx.x;
    while (rem >= 8 - bi) { rem -= 8 - bi; bi++; }
    int bj = bi + rem;
    int ib = bi * 128, jb = bj * 128;
    int tid = threadIdx.x;
    int tx = tid & 15, ty = tid >> 4;
    const float* fb = featPtr(src, off) + (size_t)b * NN * stride;

    ull acc[8][4];
#pragma unroll
    for (int i = 0; i < 8; i++)
#pragma unroll
        for (int j = 0; j < 4; j++) acc[i][j] = 0ull;

    int nch = (C + 15) >> 4;
    for (int cc = 0; cc < nch; cc++) {
#pragma unroll
        for (int l0 = 0; l0 < 8; l0++) {
            int l = l0 * 256 + tid;
            int c = l & 15, r = l >> 4;
            int cg = (cc << 4) + c;
            float a = 0.f, bv = 0.f;
            if (cg < C) {
                a = fb[(size_t)(ib + r) * stride + cg];
                bv = fb[(size_t)(jb + r) * stride + cg];
            }
            *(ull*)&Ad[c * 260 + 2 * r] = bcast2(a);
            Bs_[c * 132 + r] = bv;
        }
        __syncthreads();
#pragma unroll
        for (int c = 0; c < 16; c++) {
            const float4* arow = (const float4*)&Ad[c * 260 + ty * 16];
            const float4* brow = (const float4*)&Bs_[c * 132 + tx * 8];
            float4 bq0 = brow[0];
            float4 bq1 = brow[1];
            ull b0 = *(ull*)&bq0.x, b1 = *(ull*)&bq0.z;
            ull b2 = *(ull*)&bq1.x, b3 = *(ull*)&bq1.z;
#pragma unroll
            for (int iq = 0; iq < 4; iq++) {
                float4 aq = arow[iq];
                ull a0 = *(ull*)&aq.x;
                ull a1 = *(ull*)&aq.z;
                int i0 = 2 * iq, i1 = 2 * iq + 1;
                acc[i0][0] = ffma2(a0, b0, acc[i0][0]);
                acc[i0][1] = ffma2(a0, b1, acc[i0][1]);
                acc[i0][2] = ffma2(a0, b2, acc[i0][2]);
                acc[i0][3] = ffma2(a0, b3, acc[i0][3]);
                acc[i1][0] = ffma2(a1, b0, acc[i1][0]);
                acc[i1][1] = ffma2(a1, b1, acc[i1][1]);
                acc[i1][2] = ffma2(a1, b2, acc[i1][2]);
                acc[i1][3] = ffma2(a1, b3, acc[i1][3]);
            }
        }
        __syncthreads();
    }

    const float* xxb = g_xx + b * NN;
    float xm[8], xn[8];
#pragma unroll
    for (int j = 0; j < 8; j++) xm[j] = xxb[jb + tx * 8 + j];
#pragma unroll
    for (int i = 0; i < 8; i++) xn[i] = xxb[ib + ty * 8 + i];
    float* nd = g_nd + (size_t)b * NN * NN;

#pragma unroll
    for (int i = 0; i < 8; i++) {
        float v[8];
#pragma unroll
        for (int j = 0; j < 4; j++) unpack2(acc[i][j], v[2 * j], v[2 * j + 1]);
        float4 o0, o1;
        o0.x = 2.f * v[0] - xn[i] - xm[0];
        o0.y = 2.f * v[1] - xn[i] - xm[1];
        o0.z = 2.f * v[2] - xn[i] - xm[2];
        o0.w = 2.f * v[3] - xn[i] - xm[3];
        o1.x = 2.f * v[4] - xn[i] - xm[4];
        o1.y = 2.f * v[5] - xn[i] - xm[5];
        o1.z = 2.f * v[6] - xn[i] - xm[6];
        o1.w = 2.f * v[7] - xn[i] - xm[7];
        float4* dst = (float4*)(nd + (size_t)(ib + ty * 8 + i) * NN + jb + tx * 8);
        dst[0] = o0;
        dst[1] = o1;
    }
    if (bi != bj) {
#pragma unroll
        for (int j = 0; j < 8; j++) {
            float tmp[8];
#pragma unroll
            for (int i = 0; i < 8; i++) {
                float lo, hi;
                unpack2(acc[i][j >> 1], lo, hi);
                float mv = (j & 1) ? hi : lo;
                tmp[i] = 2.f * mv - xn[i] - xm[j];
            }
            float4* d2 = (float4*)(nd + (size_t)(jb + tx * 8 + j) * NN + ib + ty * 8);
            d2[0] = make_float4(tmp[0], tmp[1], tmp[2], tmp[3]);
            d2[1] = make_float4(tmp[4], tmp[5], tmp[6], tmp[7]);
        }
    }
}

__device__ __forceinline__ ull packkey(float v, int gidx) {
    unsigned bb = __float_as_uint(v);
    bb ^= (unsigned)(((int)bb >> 31)) | 0x80000000u;
    return ((ull)bb << 32) | (ull)(1023 - gidx);
}

// -------- fused: top-20 (blocks 0..1023) + v/u GEMM (rest) --------
__global__ __launch_bounds__(256, 4) void tk2_kernel(int src, int off, int stride,
                                                     int C, int O, int och, int woff) {
    __shared__ float sf[16 * 128];
    if (blockIdx.x < 1024) {
        int wid = threadIdx.x >> 5;
        int lane = threadIdx.x & 31;
        int rowg = blockIdx.x * 8 + wid;
        const float* row = g_nd + (size_t)rowg * NN;

        float vals[32];
#pragma unroll
        for (int j = 0; j < 32; j++) vals[j] = row[j * 32 + lane];

        unsigned alive = 0xffffffffu;
        float qv0, qv1, qv2, qv3;
        int qj0, qj1, qj2, qj3;

#define RESCANQ(Q, QV, QJ)                                            \
        {                                                             \
            QV = -3.0e38f; QJ = (Q) * 8;                              \
            _Pragma("unroll")                                         \
            for (int j0 = 0; j0 < 8; j0++) {                          \
                int j = (Q) * 8 + j0;                                 \
                float v = ((alive >> j) & 1u) ? vals[j] : -3.0e38f;   \
                if (v > QV) { QV = v; QJ = j; }                       \
            }                                                         \
        }

        RESCANQ(0, qv0, qj0)
        RESCANQ(1, qv1, qj1)
        RESCANQ(2, qv2, qj2)
        RESCANQ(3, qv3, qj3)

        float lv = qv0; int li = qj0;
        if (qv1 > lv) { lv = qv1; li = qj1; }
        if (qv2 > lv) { lv = qv2; li = qj2; }
        if (qv3 > lv) { lv = qv3; li = qj3; }

        int myout = 0;
        for (int k = 0; k < KK; k++) {
            ull key = packkey(lv, li * 32 + lane);
#pragma unroll
            for (int s = 16; s; s >>= 1) {
                ull ok = __shfl_xor_sync(0xffffffffu, key, s);
                key = (ok > key) ? ok : key;
            }
            int gidx = 1023 - (int)(key & 0xffffffffu);
            if (lane == k) myout = gidx;
            if (lane == (gidx & 31)) {
                int jrem = gidx >> 5;
                alive &= ~(1u << jrem);
                int q = jrem >> 3;
                if (q == 0)      RESCANQ(0, qv0, qj0)
                else if (q == 1) RESCANQ(1, qv1, qj1)
                else if (q == 2) RESCANQ(2, qv2, qj2)
                else             RESCANQ(3, qv3, qj3)
                lv = qv0; li = qj0;
                if (qv1 > lv) { lv = qv1; li = qj1; }
                if (qv2 > lv) { lv = qv2; li = qj2; }
                if (qv3 > lv) { lv = qv3; li = qj3; }
            }
        }
        if (lane < KK) g_idx[rowg * KK + lane] = myout;
#undef RESCANQ
    } else {
        int kb = blockIdx.x - 1024;
        int bpb = 64 * och;
        int b = kb / bpb;
        int rm = kb % bpb;
        int n0 = (rm / och) * 16;
        int o0 = (rm % och) * 64;
        int og = threadIdx.x & 63;
        int pg = threadIdx.x >> 6;
        int o = o0 + og;
        const float* fb = featPtr(src, off) + ((size_t)b * NN + n0) * stride;
        for (int l = threadIdx.x; l < 16 * C; l += 256) {
            int p = l / C, c = l % C;
            sf[p * C + c] = fb[(size_t)p * stride + c];
        }
        __syncthreads();
        float va[4], vu[4];
#pragma unroll
        for (int p = 0; p < 4; p++) { va[p] = 0.f; vu[p] = 0.f; }
        const float* wap = g_wa + woff + o;
        const float* wup = g_wu + woff + o;
        const float* sfp = sf + pg * 4 * C;
        for (int c = 0; c < C; c++) {
            float wa = wap[c * O];
            float wu = wup[c * O];
#pragma unroll
            for (int p = 0; p < 4; p++) {
                float f = sfp[p * C + c];
                va[p] = fmaf(wa, f, va[p]);
                vu[p] = fmaf(wu, f, vu[p]);
            }
        }
#pragma unroll
        for (int p = 0; p < 4; p++) {
            size_t idx = ((size_t)b * NN + n0 + pg * 4 + p) * O + o;
            g_v[idx] = va[p];
            g_u[idx] = vu[p];
        }
    }
}

// -------- gather + k-reduce + channel stats + folded BN finalize --------
// float4 per thread: c4 = tid % (O/4) owns channels 4c4..4c4+3; pp = point lane.
// 16-point strips, grid (64, BB).
__global__ __launch_bounds__(256, 8) void k3_kernel(const float* __restrict__ gam,
                          const float* __restrict__ bet, int O, int total_blocks) {
    int b = blockIdx.y;
    int n0 = blockIdx.x * 16;
    int nc4 = O >> 2;
    int c4 = threadIdx.x % nc4;
    int pp = threadIdx.x / nc4;
    int ppl = 256 / nc4;
    int ppp = 16 / ppl;
    size_t base = (size_t)b * NN;
    float4 s = make_float4(0.f, 0.f, 0.f, 0.f);
    float4 q = make_float4(0.f, 0.f, 0.f, 0.f);
    for (int p = 0; p < ppp; p++) {
        int n = n0 + pp * ppp + p;
        const int* id = g_idx + (base + n) * KK;
        float4 uu = *(const float4*)&g_u[(base + n) * O + 4 * c4];
        float4 mx = make_float4(-3.0e38f, -3.0e38f, -3.0e38f, -3.0e38f);
        float4 mn = make_float4(3.0e38f, 3.0e38f, 3.0e38f, 3.0e38f);
#pragma unroll
        for (int k = 0; k < KK; k++) {
            int j = id[k];
            float4 vv = *(const float4*)&g_v[(base + j) * O + 4 * c4];
            float y0 = vv.x + uu.x, y1 = vv.y + uu.y;
            float y2 = vv.z + uu.z, y3 = vv.w + uu.w;
            mx.x = fmaxf(mx.x, y0); mn.x = fminf(mn.x, y0);
            mx.y = fmaxf(mx.y, y1); mn.y = fminf(mn.y, y1);
            mx.z = fmaxf(mx.z, y2); mn.z = fminf(mn.z, y2);
            mx.w = fmaxf(mx.w, y3); mn.w = fminf(mn.w, y3);
            s.x += y0; s.y += y1; s.z += y2; s.w += y3;
            q.x = fmaf(y0, y0, q.x); q.y = fmaf(y1, y1, q.y);
            q.z = fmaf(y2, y2, q.z); q.w = fmaf(y3, y3, q.w);
        }
        size_t t = (base + n) * O + 4 * c4;
        *(float4*)&g_maxv[t] = mx;
        *(float4*)&g_minv[t] = mn;
    }
    atomicAdd(&g_sum[4 * c4 + 0], s.x);
    atomicAdd(&g_sum[4 * c4 + 1], s.y);
    atomicAdd(&g_sum[4 * c4 + 2], s.z);
    atomicAdd(&g_sum[4 * c4 + 3], s.w);
    atomicAdd(&g_sq[4 * c4 + 0], q.x);
    atomicAdd(&g_sq[4 * c4 + 1], q.y);
    atomicAdd(&g_sq[4 * c4 + 2], q.z);
    atomicAdd(&g_sq[4 * c4 + 3], q.w);

    __threadfence();
    __shared__ int isLast;
    if (threadIdx.x == 0) isLast = (atomicAdd(&g_cnt, 1) == total_blocks - 1);
    __syncthreads();
    if (isLast && threadIdx.x < O) {
        int o = threadIdx.x;
        volatile float* vs = g_sum;
        volatile float* vq = g_sq;
        float cnt = (float)(BB * NN * KK);
        float m = vs[o] / cnt;
        float var = vq[o] / cnt - m * m;
        float sc = gam[o] * rsqrtf(var + 1e-5f);
        g_scale[o] = sc;
        g_bias[o] = bet[o] - m * sc;
        if (o == 0) g_cnt = 0;
    }
}

// -------- BN+lrelu apply -> cat ; fused next-layer xx ; zero stats --------
__global__ void k4b(int O, int coff, int do_xx) {
    __shared__ float sq_s[8];
    if (blockIdx.x == 0) {
        for (int z = threadIdx.x; z < O5; z += 256) { g_sum[z] = 0.f; g_sq[z] = 0.f; }
    }
    int t = blockIdx.x * 256 + threadIdx.x;
    int o = t % O;
    size_t pn = t / O;
    float sc = g_scale[o], bi = g_bias[o];
    float sel = (sc >= 0.f) ? g_maxv[t] : g_minv[t];
    float y = fmaf(sc, sel, bi);
    float act = (y >= 0.f) ? y : 0.2f * y;
    g_cat[pn * CAT + coff + o] = act;
    if (do_xx) {
        float q = act * act;
#pragma unroll
        for (int s = 16; s; s >>= 1) q += __shfl_xor_sync(0xffffffffu, q, s);
        if ((threadIdx.x & 31) == 0) sq_s[threadIdx.x >> 5] = q;
        __syncthreads();
        int pts = 256 / O, wpp = O / 32;
        if (threadIdx.x < pts) {
            float a = 0.f;
            for (int w = 0; w < wpp; w++) a += sq_s[threadIdx.x * wpp + w];
            g_xx[(size_t)blockIdx.x * pts + threadIdx.x] = a;
        }
    }
}

// -------- final conv1d GEMM: 128x128 tile, 8x8 micro, f32x2, fused n-stats --------
__global__ __launch_bounds__(256, 2) void f1_kernel(const float* __restrict__ W5) {
    __shared__ __align__(16) float Ad[16 * 260];
    __shared__ __align__(16) float Bs_[16 * 132];
    int ob = blockIdx.x * 128;
    int nb = blockIdx.y * 128;
    int b = blockIdx.z;
    int tid = threadIdx.x;
    int tx = tid & 15, ty = tid >> 4;
    const float* cb = g_cat + (size_t)b * NN * CAT;

    ull acc[8][4];
#pragma unroll
    for (int i = 0; i < 8; i++)
#pragma unroll
        for (int j = 0; j < 4; j++) acc[i][j] = 0ull;

    for (int cc = 0; cc < 32; cc++) {
#pragma unroll
        for (int l0 = 0; l0 < 8; l0++) {
            int l = l0 * 256 + tid;
            int c = l & 15, r = l >> 4;
            float a = W5[(size_t)(ob + r) * 512 + (cc << 4) + c];
            float bv = cb[(size_t)(nb + r) * 512 + (cc << 4) + c];
            *(ull*)&Ad[c * 260 + 2 * r] = bcast2(a);
            Bs_[c * 132 + r] = bv;
        }
        __syncthreads();
#pragma unroll
        for (int c = 0; c < 16; c++) {
            const float4* arow = (const float4*)&Ad[c * 260 + ty * 16];
            const float4* brow = (const float4*)&Bs_[c * 132 + tx * 8];
            float4 bq0 = brow[0];
            float4 bq1 = brow[1];
            ull b0 = *(ull*)&bq0.x, b1 = *(ull*)&bq0.z;
            ull b2 = *(ull*)&bq1.x, b3 = *(ull*)&bq1.z;
#pragma unroll
            for (int iq = 0; iq < 4; iq++) {
                float4 aq = arow[iq];
                ull a0 = *(ull*)&aq.x;
                ull a1 = *(ull*)&aq.z;
                int i0 = 2 * iq, i1 = 2 * iq + 1;
                acc[i0][0] = ffma2(a0, b0, acc[i0][0]);
                acc[i0][1] = ffma2(a0, b1, acc[i0][1]);
                acc[i0][2] = ffma2(a0, b2, acc[i0][2]);
                acc[i0][3] = ffma2(a0, b3, acc[i0][3]);
                acc[i1][0] = ffma2(a1, b0, acc[i1][0]);
                acc[i1][1] = ffma2(a1, b1, acc[i1][1]);
                acc[i1][2] = ffma2(a1, b2, acc[i1][2]);
                acc[i1][3] = ffma2(a1, b3, acc[i1][3]);
            }
        }
        __syncthreads();
    }

#pragma unroll
    for (int i = 0; i < 8; i++) {
        float v[8];
#pragma unroll
        for (int j = 0; j < 4; j++) unpack2(acc[i][j], v[2 * j], v[2 * j + 1]);
        float mx = v[0], mn = v[0], s = v[0], q = v[0] * v[0];
#pragma unroll
        for (int j = 1; j < 8; j++) {
            mx = fmaxf(mx, v[j]);
            mn = fminf(mn, v[j]);
            s += v[j];
            q = fmaf(v[j], v[j], q);
        }
#pragma unroll
        for (int st = 8; st; st >>= 1) {
            mx = fmaxf(mx, __shfl_xor_sync(0xffffffffu, mx, st));
            mn = fminf(mn, __shfl_xor_sync(0xffffffffu, mn, st));
            s += __shfl_xor_sync(0xffffffffu, s, st);
            q += __shfl_xor_sync(0xffffffffu, q, st);
        }
        if (tx == 0) {
            int o = ob + ty * 8 + i;
            g_pmax[((size_t)b * O5 + o) * 8 + blockIdx.y] = mx;
            g_pmin[((size_t)b * O5 + o) * 8 + blockIdx.y] = mn;
            atomicAdd(&g_sum[o], s);
            atomicAdd(&g_sq[o], q);
        }
    }
}

// -------- final BN + lrelu + max over n --------
__global__ void f2_kernel(const float* __restrict__ g5, const float* __restrict__ b5,
                          float* __restrict__ out) {
    int t = blockIdx.x * blockDim.x + threadIdx.x;
    if (t >= BB * O5) return;
    int b = t / O5, o = t % O5;
    float m = g_sum[o] / 8192.f;
    float var = g_sq[o] / 8192.f - m * m;
    float sc = g5[o] * rsqrtf(var + 1e-5f);
    float bi = b5[o] - m * sc;
    size_t base = ((size_t)b * O5 + o) * 8;
    float sel;
    if (sc >= 0.f) {
        sel = g_pmax[base];
        for (int i = 1; i < 8; i++) sel = fmaxf(sel, g_pmax[base + i]);
    } else {
        sel = g_pmin[base];
        for (int i = 1; i < 8; i++) sel = fminf(sel, g_pmin[base + i]);
    }
    float y = fmaf(sc, sel, bi);
    out[t] = (y >= 0.f) ? y : 0.2f * y;
}

extern "C" void kernel_launch(void* const* d_in, const int* in_sizes, int n_in,
                              void* d_out, int out_size) {
    const float* x  = (const float*)d_in[0];
    const float* Wl[4] = {(const float*)d_in[1], (const float*)d_in[4],
                          (const float*)d_in[7], (const float*)d_in[10]};
    const float* gl[4] = {(const float*)d_in[2], (const float*)d_in[5],
                          (const float*)d_in[8], (const float*)d_in[11]};
    const float* bl[4] = {(const float*)d_in[3], (const float*)d_in[6],
                          (const float*)d_in[9], (const float*)d_in[12]};
    const float* W5 = (const float*)d_in[13];
    const float* g5 = (const float*)d_in[14];
    const float* b5 = (const float*)d_in[15];
    float* out = (float*)d_out;

    prep0<<<210, 256>>>(x, Wl[0], Wl[1], Wl[2], Wl[3]);

    const int srcA[4]  = {0, 1, 1, 1};
    const int offA[4]  = {0, 0, 64, 128};
    const int CA[4]    = {3, 64, 64, 128};
    const int OA[4]    = {64, 64, 128, 256};
    const int coffA[4] = {0, 64, 128, 256};
    const int woffA[4] = {0, 256, 4608, 12800};

    for (int L = 0; L < 4; L++) {
        int src = srcA[L], off = offA[L], C = CA[L], O = OA[L], coff = coffA[L];
        int woff = woffA[L];
        int stride = src ? CAT : 4;
        int och = O / 64;
        kd_kernel<<<dim3(36, 1, BB), 256>>>(src, off, stride, C);
        tk2_kernel<<<1024 + 512 * och, 256>>>(src, off, stride, C, O, och, woff);
        k3_kernel<<<dim3(64, BB), 256>>>(gl[L], bl[L], O, 512);
        k4b<<<BB * NN * O / 256, 256>>>(O, coff, (L < 3) ? 1 : 0);
    }

    f1_kernel<<<dim3(8, 8, BB), 256>>>(W5);
    f2_kernel<<<32, 256>>>(g5, b5, out);
}

// round 9
// speedup vs baseline: 1.6377x; 1.6377x over previous
#include <cuda_runtime.h>

#define BB 8
#define NN 1024
#define KK 20
#define CAT 512
#define O5 1024

typedef unsigned long long ull;

__device__ __forceinline__ ull ffma2(ull a, ull b, ull c) {
    ull d;
    asm("fma.rn.f32x2 %0, %1, %2, %3;" : "=l"(d) : "l"(a), "l"(b), "l"(c));
    return d;
}
__device__ __forceinline__ ull bcast2(float v) {
    ull d;
    asm("mov.b64 %0, {%1, %1};" : "=l"(d) : "f"(v));
    return d;
}
__device__ __forceinline__ void unpack2(ull p, float& lo, float& hi) {
    asm("mov.b64 {%0, %1}, %2;" : "=f"(lo), "=f"(hi) : "l"(p));
}

// -------- static device workspaces --------
__device__ float g_f0[BB * NN * 4];
__device__ float g_cat[BB * NN * CAT];
__device__ float g_xx[BB * NN];
__device__ float g_nd[BB * NN * NN];
__device__ int   g_idx[BB * NN * KK];
__device__ float g_v[BB * NN * 256];
__device__ float g_u[BB * NN * 256];
__device__ float g_wa[64 * 1024];
__device__ float g_wu[64 * 1024];
__device__ float g_maxv[BB * NN * 256];
__device__ float g_minv[BB * NN * 256];
__device__ float g_sum[O5];
__device__ float g_sq[O5];
__device__ float g_pmax[BB * O5 * 8];
__device__ float g_pmin[BB * O5 * 8];
__device__ float g_scale[256];
__device__ float g_bias[256];
__device__ int   g_cnt;

__device__ __forceinline__ const float* featPtr(int src, int off) {
    return src ? (g_cat + off) : g_f0;
}

// -------- fused prep: transpose x + xx(layer1) + ALL W splits + zero stats --------
__global__ void prep0(const float* __restrict__ x,
                      const float* __restrict__ W1, const float* __restrict__ W2,
                      const float* __restrict__ W3, const float* __restrict__ W4) {
    int bx = blockIdx.x;
    if (bx < 32) {
        int t = bx * 256 + threadIdx.x;
        int b = t / NN, n = t % NN;
        float x0 = x[(b * 3 + 0) * NN + n];
        float x1 = x[(b * 3 + 1) * NN + n];
        float x2 = x[(b * 3 + 2) * NN + n];
        float* d = g_f0 + (size_t)t * 4;
        d[0] = x0; d[1] = x1; d[2] = x2; d[3] = 0.f;
        float a = fmaf(x0, x0, 0.f);
        a = fmaf(x1, x1, a);
        a = fmaf(x2, x2, a);
        g_xx[t] = a;
    } else if (bx == 32) {
        for (int t = threadIdx.x; t < O5; t += 256) { g_sum[t] = 0.f; g_sq[t] = 0.f; }
    } else {
        int t = (bx - 33) * 256 + threadIdx.x;
        const float* W; int C, O, woff, local;
        if (t < 192)        { W = W1; C = 3;   O = 64;  woff = 0;     local = t; }
        else if (t < 4288)  { W = W2; C = 64;  O = 64;  woff = 256;   local = t - 192; }
        else if (t < 12480) { W = W3; C = 64;  O = 128; woff = 4608;  local = t - 4288; }
        else if (t < 45248) { W = W4; C = 128; O = 256; woff = 12800; local = t - 12480; }
        else return;
        int c = local / O, o = local % O;
        float wa = W[o * (2 * C) + c];
        float wb = W[o * (2 * C) + C + c];
        g_wa[woff + c * O + o] = wa;
        g_wu[woff + c * O + o] = wb - wa;
    }
}

// -------- neg pairwise distance Gram GEMM: symmetric, 128x128 tile, 8x8, f32x2 --------
// Register-prefetch double buffering: next chunk's LDGs issue before compute.
__global__ __launch_bounds__(256, 2) void kd_kernel(int src, int off, int stride, int C) {
    __shared__ __align__(16) float Ad[16 * 260];
    __shared__ __align__(16) float Bs_[16 * 132];
    int b = blockIdx.z;
    int bi = 0, rem = blockIdx.x;
    while (rem >= 8 - bi) { rem -= 8 - bi; bi++; }
    int bj = bi + rem;
    int ib = bi * 128, jb = bj * 128;
    int tid = threadIdx.x;
    int tx = tid & 15, ty = tid >> 4;
    const float* fb = featPtr(src, off) + (size_t)b * NN * stride;

    ull acc[8][4];
#pragma unroll
    for (int i = 0; i < 8; i++)
#pragma unroll
        for (int j = 0; j < 4; j++) acc[i][j] = 0ull;

    int nch = (C + 15) >> 4;
    float pa[8], pb[8];
    {
        int c = tid & 15;
#pragma unroll
        for (int l0 = 0; l0 < 8; l0++) {
            int r = (l0 * 256 + tid) >> 4;
            float a = 0.f, bv = 0.f;
            if (c < C) {
                a = fb[(size_t)(ib + r) * stride + c];
                bv = fb[(size_t)(jb + r) * stride + c];
            }
            pa[l0] = a; pb[l0] = bv;
        }
    }
    for (int cc = 0; cc < nch; cc++) {
        int c = tid & 15;
#pragma unroll
        for (int l0 = 0; l0 < 8; l0++) {
            int r = (l0 * 256 + tid) >> 4;
            *(ull*)&Ad[c * 260 + 2 * r] = bcast2(pa[l0]);
            Bs_[c * 132 + r] = pb[l0];
        }
        __syncthreads();
        if (cc + 1 < nch) {
            int cg = ((cc + 1) << 4) + c;
#pragma unroll
            for (int l0 = 0; l0 < 8; l0++) {
                int r = (l0 * 256 + tid) >> 4;
                float a = 0.f, bv = 0.f;
                if (cg < C) {
                    a = fb[(size_t)(ib + r) * stride + cg];
                    bv = fb[(size_t)(jb + r) * stride + cg];
                }
                pa[l0] = a; pb[l0] = bv;
            }
        }
#pragma unroll
        for (int cs = 0; cs < 16; cs++) {
            const float4* arow = (const float4*)&Ad[cs * 260 + ty * 16];
            const float4* brow = (const float4*)&Bs_[cs * 132 + tx * 8];
            float4 bq0 = brow[0];
            float4 bq1 = brow[1];
            ull b0 = *(ull*)&bq0.x, b1 = *(ull*)&bq0.z;
            ull b2 = *(ull*)&bq1.x, b3 = *(ull*)&bq1.z;
#pragma unroll
            for (int iq = 0; iq < 4; iq++) {
                float4 aq = arow[iq];
                ull a0 = *(ull*)&aq.x;
                ull a1 = *(ull*)&aq.z;
                int i0 = 2 * iq, i1 = 2 * iq + 1;
                acc[i0][0] = ffma2(a0, b0, acc[i0][0]);
                acc[i0][1] = ffma2(a0, b1, acc[i0][1]);
                acc[i0][2] = ffma2(a0, b2, acc[i0][2]);
                acc[i0][3] = ffma2(a0, b3, acc[i0][3]);
                acc[i1][0] = ffma2(a1, b0, acc[i1][0]);
                acc[i1][1] = ffma2(a1, b1, acc[i1][1]);
                acc[i1][2] = ffma2(a1, b2, acc[i1][2]);
                acc[i1][3] = ffma2(a1, b3, acc[i1][3]);
            }
        }
        __syncthreads();
    }

    const float* xxb = g_xx + b * NN;
    float xm[8], xn[8];
#pragma unroll
    for (int j = 0; j < 8; j++) xm[j] = xxb[jb + tx * 8 + j];
#pragma unroll
    for (int i = 0; i < 8; i++) xn[i] = xxb[ib + ty * 8 + i];
    float* nd = g_nd + (size_t)b * NN * NN;

#pragma unroll
    for (int i = 0; i < 8; i++) {
        float v[8];
#pragma unroll
        for (int j = 0; j < 4; j++) unpack2(acc[i][j], v[2 * j], v[2 * j + 1]);
        float4 o0, o1;
        o0.x = 2.f * v[0] - xn[i] - xm[0];
        o0.y = 2.f * v[1] - xn[i] - xm[1];
        o0.z = 2.f * v[2] - xn[i] - xm[2];
        o0.w = 2.f * v[3] - xn[i] - xm[3];
        o1.x = 2.f * v[4] - xn[i] - xm[4];
        o1.y = 2.f * v[5] - xn[i] - xm[5];
        o1.z = 2.f * v[6] - xn[i] - xm[6];
        o1.w = 2.f * v[7] - xn[i] - xm[7];
        float4* dst = (float4*)(nd + (size_t)(ib + ty * 8 + i) * NN + jb + tx * 8);
        dst[0] = o0;
        dst[1] = o1;
    }
    if (bi != bj) {
#pragma unroll
        for (int j = 0; j < 8; j++) {
            float tmp[8];
#pragma unroll
            for (int i = 0; i < 8; i++) {
                float lo, hi;
                unpack2(acc[i][j >> 1], lo, hi);
                float mv = (j & 1) ? hi : lo;
                tmp[i] = 2.f * mv - xn[i] - xm[j];
            }
            float4* d2 = (float4*)(nd + (size_t)(jb + tx * 8 + j) * NN + ib + ty * 8);
            d2[0] = make_float4(tmp[0], tmp[1], tmp[2], tmp[3]);
            d2[1] = make_float4(tmp[4], tmp[5], tmp[6], tmp[7]);
        }
    }
}

__device__ __forceinline__ ull packkey(float v, int gidx) {
    unsigned bb = __float_as_uint(v);
    bb ^= (unsigned)(((int)bb >> 31)) | 0x80000000u;
    return ((ull)bb << 32) | (ull)(1023 - gidx);
}

// -------- fused: top-20 (blocks 0..1023) + v/u GEMM (rest) --------
__global__ __launch_bounds__(256, 4) void tk2_kernel(int src, int off, int stride,
                                                     int C, int O, int och, int woff) {
    __shared__ float sf[16 * 128];
    if (blockIdx.x < 1024) {
        int wid = threadIdx.x >> 5;
        int lane = threadIdx.x & 31;
        int rowg = blockIdx.x * 8 + wid;
        const float* row = g_nd + (size_t)rowg * NN;

        float vals[32];
#pragma unroll
        for (int j = 0; j < 32; j++) vals[j] = row[j * 32 + lane];

        unsigned alive = 0xffffffffu;
        float qv0, qv1, qv2, qv3;
        int qj0, qj1, qj2, qj3;

#define RESCANQ(Q, QV, QJ)                                            \
        {                                                             \
            QV = -3.0e38f; QJ = (Q) * 8;                              \
            _Pragma("unroll")                                         \
            for (int j0 = 0; j0 < 8; j0++) {                          \
                int j = (Q) * 8 + j0;                                 \
                float v = ((alive >> j) & 1u) ? vals[j] : -3.0e38f;   \
                if (v > QV) { QV = v; QJ = j; }                       \
            }                                                         \
        }

        RESCANQ(0, qv0, qj0)
        RESCANQ(1, qv1, qj1)
        RESCANQ(2, qv2, qj2)
        RESCANQ(3, qv3, qj3)

        float lv = qv0; int li = qj0;
        if (qv1 > lv) { lv = qv1; li = qj1; }
        if (qv2 > lv) { lv = qv2; li = qj2; }
        if (qv3 > lv) { lv = qv3; li = qj3; }

        int myout = 0;
        for (int k = 0; k < KK; k++) {
            ull key = packkey(lv, li * 32 + lane);
#pragma unroll
            for (int s = 16; s; s >>= 1) {
                ull ok = __shfl_xor_sync(0xffffffffu, key, s);
                key = (ok > key) ? ok : key;
            }
            int gidx = 1023 - (int)(key & 0xffffffffu);
            if (lane == k) myout = gidx;
            if (lane == (gidx & 31)) {
                int jrem = gidx >> 5;
                alive &= ~(1u << jrem);
                int q = jrem >> 3;
                if (q == 0)      RESCANQ(0, qv0, qj0)
                else if (q == 1) RESCANQ(1, qv1, qj1)
                else if (q == 2) RESCANQ(2, qv2, qj2)
                else             RESCANQ(3, qv3, qj3)
                lv = qv0; li = qj0;
                if (qv1 > lv) { lv = qv1; li = qj1; }
                if (qv2 > lv) { lv = qv2; li = qj2; }
                if (qv3 > lv) { lv = qv3; li = qj3; }
            }
        }
        if (lane < KK) g_idx[rowg * KK + lane] = myout;
#undef RESCANQ
    } else {
        int kb = blockIdx.x - 1024;
        int bpb = 64 * och;
        int b = kb / bpb;
        int rm = kb % bpb;
        int n0 = (rm / och) * 16;
        int o0 = (rm % och) * 64;
        int og = threadIdx.x & 63;
        int pg = threadIdx.x >> 6;
        int o = o0 + og;
        const float* fb = featPtr(src, off) + ((size_t)b * NN + n0) * stride;
        for (int l = threadIdx.x; l < 16 * C; l += 256) {
            int p = l / C, c = l % C;
            sf[p * C + c] = fb[(size_t)p * stride + c];
        }
        __syncthreads();
        float va[4], vu[4];
#pragma unroll
        for (int p = 0; p < 4; p++) { va[p] = 0.f; vu[p] = 0.f; }
        const float* wap = g_wa + woff + o;
        const float* wup = g_wu + woff + o;
        const float* sfp = sf + pg * 4 * C;
        for (int c = 0; c < C; c++) {
            float wa = wap[c * O];
            float wu = wup[c * O];
#pragma unroll
            for (int p = 0; p < 4; p++) {
                float f = sfp[p * C + c];
                va[p] = fmaf(wa, f, va[p]);
                vu[p] = fmaf(wu, f, vu[p]);
            }
        }
#pragma unroll
        for (int p = 0; p < 4; p++) {
            size_t idx = ((size_t)b * NN + n0 + pg * 4 + p) * O + o;
            g_v[idx] = va[p];
            g_u[idx] = vu[p];
        }
    }
}

// -------- gather + k-reduce + channel stats + folded BN finalize --------
// R6 form: scalar gather, 16-point strips, grid (64, BB), 2 atomics/thread.
__global__ __launch_bounds__(256, 8) void k3_kernel(const float* __restrict__ gam,
                          const float* __restrict__ bet, int O, int total_blocks) {
    int b = blockIdx.y;
    int n0 = blockIdx.x * 16;
    int o = threadIdx.x % O;
    int pp = threadIdx.x / O;
    int ppl = 256 / O;
    int ppp = 16 / ppl;                  // points per lane
    size_t base = (size_t)b * NN;
    float s = 0.f, q = 0.f;
    for (int p = 0; p < ppp; p++) {
        int n = n0 + pp * ppp + p;
        const int* id = g_idx + (base + n) * KK;
        float uu = g_u[(base + n) * O + o];
        float mx = -3.0e38f, mn = 3.0e38f;
#pragma unroll
        for (int k = 0; k < KK; k++) {
            int j = id[k];
            float y = g_v[(base + j) * O + o] + uu;
            mx = fmaxf(mx, y);
            mn = fminf(mn, y);
            s += y;
            q = fmaf(y, y, q);
        }
        size_t t = (base + n) * O + o;
        g_maxv[t] = mx;
        g_minv[t] = mn;
    }
    atomicAdd(&g_sum[o], s);
    atomicAdd(&g_sq[o], q);

    __threadfence();
    __shared__ int isLast;
    if (threadIdx.x == 0) isLast = (atomicAdd(&g_cnt, 1) == total_blocks - 1);
    __syncthreads();
    if (isLast && threadIdx.x < O) {
        volatile float* vs = g_sum;
        volatile float* vq = g_sq;
        float cnt = (float)(BB * NN * KK);
        float m = vs[o] / cnt;
        float var = vq[o] / cnt - m * m;
        float sc = gam[o] * rsqrtf(var + 1e-5f);
        g_scale[o] = sc;
        g_bias[o] = bet[o] - m * sc;
        if (o == 0) g_cnt = 0;
    }
}

// -------- BN+lrelu apply -> cat ; fused next-layer xx ; zero stats --------
__global__ void k4b(int O, int coff, int do_xx) {
    __shared__ float sq_s[8];
    if (blockIdx.x == 0) {
        for (int z = threadIdx.x; z < O5; z += 256) { g_sum[z] = 0.f; g_sq[z] = 0.f; }
    }
    int t = blockIdx.x * 256 + threadIdx.x;
    int o = t % O;
    size_t pn = t / O;
    float sc = g_scale[o], bi = g_bias[o];
    float sel = (sc >= 0.f) ? g_maxv[t] : g_minv[t];
    float y = fmaf(sc, sel, bi);
    float act = (y >= 0.f) ? y : 0.2f * y;
    g_cat[pn * CAT + coff + o] = act;
    if (do_xx) {
        float q = act * act;
#pragma unroll
        for (int s = 16; s; s >>= 1) q += __shfl_xor_sync(0xffffffffu, q, s);
        if ((threadIdx.x & 31) == 0) sq_s[threadIdx.x >> 5] = q;
        __syncthreads();
        int pts = 256 / O, wpp = O / 32;
        if (threadIdx.x < pts) {
            float a = 0.f;
            for (int w = 0; w < wpp; w++) a += sq_s[threadIdx.x * wpp + w];
            g_xx[(size_t)blockIdx.x * pts + threadIdx.x] = a;
        }
    }
}

// -------- final conv1d GEMM: 128x128 tile, 8x8, f32x2, prefetch, fused n-stats --------
__global__ __launch_bounds__(256, 2) void f1_kernel(const float* __restrict__ W5) {
    __shared__ __align__(16) float Ad[16 * 260];
    __shared__ __align__(16) float Bs_[16 * 132];
    int ob = blockIdx.x * 128;
    int nb = blockIdx.y * 128;
    int b = blockIdx.z;
    int tid = threadIdx.x;
    int tx = tid & 15, ty = tid >> 4;
    const float* cb = g_cat + (size_t)b * NN * CAT;

    ull acc[8][4];
#pragma unroll
    for (int i = 0; i < 8; i++)
#pragma unroll
        for (int j = 0; j < 4; j++) acc[i][j] = 0ull;

    float pa[8], pb[8];
    {
        int c = tid & 15;
#pragma unroll
        for (int l0 = 0; l0 < 8; l0++) {
            int r = (l0 * 256 + tid) >> 4;
            pa[l0] = W5[(size_t)(ob + r) * 512 + c];
            pb[l0] = cb[(size_t)(nb + r) * 512 + c];
        }
    }
    for (int cc = 0; cc < 32; cc++) {
        int c = tid & 15;
#pragma unroll
        for (int l0 = 0; l0 < 8; l0++) {
            int r = (l0 * 256 + tid) >> 4;
            *(ull*)&Ad[c * 260 + 2 * r] = bcast2(pa[l0]);
            Bs_[c * 132 + r] = pb[l0];
        }
        __syncthreads();
        if (cc < 31) {
            int cg = ((cc + 1) << 4) + c;
#pragma unroll
            for (int l0 = 0; l0 < 8; l0++) {
                int r = (l0 * 256 + tid) >> 4;
                pa[l0] = W5[(size_t)(ob + r) * 512 + cg];
                pb[l0] = cb[(size_t)(nb + r) * 512 + cg];
            }
        }
#pragma unroll
        for (int cs = 0; cs < 16; cs++) {
            const float4* arow = (const float4*)&Ad[cs * 260 + ty * 16];
            const float4* brow = (const float4*)&Bs_[cs * 132 + tx * 8];
            float4 bq0 = brow[0];
            float4 bq1 = brow[1];
            ull b0 = *(ull*)&bq0.x, b1 = *(ull*)&bq0.z;
            ull b2 = *(ull*)&bq1.x, b3 = *(ull*)&bq1.z;
#pragma unroll
            for (int iq = 0; iq < 4; iq++) {
                float4 aq = arow[iq];
                ull a0 = *(ull*)&aq.x;
                ull a1 = *(ull*)&aq.z;
                int i0 = 2 * iq, i1 = 2 * iq + 1;
                acc[i0][0] = ffma2(a0, b0, acc[i0][0]);
                acc[i0][1] = ffma2(a0, b1, acc[i0][1]);
                acc[i0][2] = ffma2(a0, b2, acc[i0][2]);
                acc[i0][3] = ffma2(a0, b3, acc[i0][3]);
                acc[i1][0] = ffma2(a1, b0, acc[i1][0]);
                acc[i1][1] = ffma2(a1, b1, acc[i1][1]);
                acc[i1][2] = ffma2(a1, b2, acc[i1][2]);
                acc[i1][3] = ffma2(a1, b3, acc[i1][3]);
            }
        }
        __syncthreads();
    }

#pragma unroll
    for (int i = 0; i < 8; i++) {
        float v[8];
#pragma unroll
        for (int j = 0; j < 4; j++) unpack2(acc[i][j], v[2 * j], v[2 * j + 1]);
        float mx = v[0], mn = v[0], s = v[0], q = v[0] * v[0];
#pragma unroll
        for (int j = 1; j < 8; j++) {
            mx = fmaxf(mx, v[j]);
            mn = fminf(mn, v[j]);
            s += v[j];
            q = fmaf(v[j], v[j], q);
        }
#pragma unroll
        for (int st = 8; st; st >>= 1) {
            mx = fmaxf(mx, __shfl_xor_sync(0xffffffffu, mx, st));
            mn = fminf(mn, __shfl_xor_sync(0xffffffffu, mn, st));
            s += __shfl_xor_sync(0xffffffffu, s, st);
            q += __shfl_xor_sync(0xffffffffu, q, st);
        }
        if (tx == 0) {
            int o = ob + ty * 8 + i;
            g_pmax[((size_t)b * O5 + o) * 8 + blockIdx.y] = mx;
            g_pmin[((size_t)b * O5 + o) * 8 + blockIdx.y] = mn;
            atomicAdd(&g_sum[o], s);
            atomicAdd(&g_sq[o], q);
        }
    }
}

// -------- final BN + lrelu + max over n --------
__global__ void f2_kernel(const float* __restrict__ g5, const float* __restrict__ b5,
                          float* __restrict__ out) {
    int t = blockIdx.x * blockDim.x + threadIdx.x;
    if (t >= BB * O5) return;
    int b = t / O5, o = t % O5;
    float m = g_sum[o] / 8192.f;
    float var = g_sq[o] / 8192.f - m * m;
    float sc = g5[o] * rsqrtf(var + 1e-5f);
    float bi = b5[o] - m * sc;
    size_t base = ((size_t)b * O5 + o) * 8;
    float sel;
    if (sc >= 0.f) {
        sel = g_pmax[base];
        for (int i = 1; i < 8; i++) sel = fmaxf(sel, g_pmax[base + i]);
    } else {
        sel = g_pmin[base];
        for (int i = 1; i < 8; i++) sel = fminf(sel, g_pmin[base + i]);
    }
    float y = fmaf(sc, sel, bi);
    out[t] = (y >= 0.f) ? y : 0.2f * y;
}

extern "C" void kernel_launch(void* const* d_in, const int* in_sizes, int n_in,
                              void* d_out, int out_size) {
    const float* x  = (const float*)d_in[0];
    const float* Wl[4] = {(const float*)d_in[1], (const float*)d_in[4],
                          (const float*)d_in[7], (const float*)d_in[10]};
    const float* gl[4] = {(const float*)d_in[2], (const float*)d_in[5],
                          (const float*)d_in[8], (const float*)d_in[11]};
    const float* bl[4] = {(const float*)d_in[3], (const float*)d_in[6],
                          (const float*)d_in[9], (const float*)d_in[12]};
    const float* W5 = (const float*)d_in[13];
    const float* g5 = (const float*)d_in[14];
    const float* b5 = (const float*)d_in[15];
    float* out = (float*)d_out;

    prep0<<<210, 256>>>(x, Wl[0], Wl[1], Wl[2], Wl[3]);

    const int srcA[4]  = {0, 1, 1, 1};
    const int offA[4]  = {0, 0, 64, 128};
    const int CA[4]    = {3, 64, 64, 128};
    const int OA[4]    = {64, 64, 128, 256};
    const int coffA[4] = {0, 64, 128, 256};
    const int woffA[4] = {0, 256, 4608, 12800};

    for (int L = 0; L < 4; L++) {
        int src = srcA[L], off = offA[L], C = CA[L], O = OA[L], coff = coffA[L];
        int woff = woffA[L];
        int stride = src ? CAT : 4;
        int och = O / 64;
        kd_kernel<<<dim3(36, 1, BB), 256>>>(src, off, stride, C);
        tk2_kernel<<<1024 + 512 * och, 256>>>(src, off, stride, C, O, och, woff);
        k3_kernel<<<dim3(64, BB), 256>>>(gl[L], bl[L], O, 512);
        k4b<<<BB * NN * O / 256, 256>>>(O, coff, (L < 3) ? 1 : 0);
    }

    f1_kernel<<<dim3(8, 8, BB), 256>>>(W5);
    f2_kernel<<<32, 256>>>(g5, b5, out);
}

// round 11
// speedup vs baseline: 1.7030x; 1.0399x over previous
#include <cuda_runtime.h>

#define BB 8
#define NN 1024
#define KK 20
#define CAT 512
#define O5 1024

typedef unsigned long long ull;

__device__ __forceinline__ ull ffma2(ull a, ull b, ull c) {
    ull d;
    asm("fma.rn.f32x2 %0, %1, %2, %3;" : "=l"(d) : "l"(a), "l"(b), "l"(c));
    return d;
}
__device__ __forceinline__ ull bcast2(float v) {
    ull d;
    asm("mov.b64 %0, {%1, %1};" : "=l"(d) : "f"(v));
    return d;
}
__device__ __forceinline__ void unpack2(ull p, float& lo, float& hi) {
    asm("mov.b64 {%0, %1}, %2;" : "=f"(lo), "=f"(hi) : "l"(p));
}

// -------- static device workspaces --------
__device__ float g_f0[BB * NN * 4];
__device__ float g_cat[BB * NN * CAT];
__device__ float g_xx[BB * NN];
__device__ float g_nd[BB * NN * NN];
__device__ int   g_idx[BB * NN * KK];
__device__ float g_v[BB * NN * 256];
__device__ float g_u[BB * NN * 256];
__device__ __align__(8) float g_wa[64 * 1024];   // packed: pair-major {w[c],w[c+1]}
__device__ __align__(8) float g_wu[64 * 1024];
__device__ float g_maxv[BB * NN * 256];
__device__ float g_minv[BB * NN * 256];
__device__ float g_sum[O5];
__device__ float g_sq[O5];
__device__ float g_pmax[BB * O5 * 8];
__device__ float g_pmin[BB * O5 * 8];
__device__ float g_scale[256];
__device__ float g_bias[256];
__device__ int   g_cnt;

__device__ __forceinline__ const float* featPtr(int src, int off) {
    return src ? (g_cat + off) : g_f0;
}

// -------- fused prep: transpose x + xx(layer1) + ALL W splits (pair-packed) + zero stats --------
__global__ void prep0(const float* __restrict__ x,
                      const float* __restrict__ W1, const float* __restrict__ W2,
                      const float* __restrict__ W3, const float* __restrict__ W4) {
    int bx = blockIdx.x;
    if (bx < 32) {
        int t = bx * 256 + threadIdx.x;
        int b = t / NN, n = t % NN;
        float x0 = x[(b * 3 + 0) * NN + n];
        float x1 = x[(b * 3 + 1) * NN + n];
        float x2 = x[(b * 3 + 2) * NN + n];
        float* d = g_f0 + (size_t)t * 4;
        d[0] = x0; d[1] = x1; d[2] = x2; d[3] = 0.f;
        float a = fmaf(x0, x0, 0.f);
        a = fmaf(x1, x1, a);
        a = fmaf(x2, x2, a);
        g_xx[t] = a;
    } else if (bx == 32) {
        for (int t = threadIdx.x; t < O5; t += 256) { g_sum[t] = 0.f; g_sq[t] = 0.f; }
    } else {
        int t = (bx - 33) * 256 + threadIdx.x;
        const float* W; int C, O, woff, local;
        if (t < 256)        { W = W1; C = 3;   O = 64;  woff = 0;     local = t; }          // CP=4
        else if (t < 4352)  { W = W2; C = 64;  O = 64;  woff = 256;   local = t - 256; }
        else if (t < 12544) { W = W3; C = 64;  O = 128; woff = 4352;  local = t - 4352; }
        else if (t < 45312) { W = W4; C = 128; O = 256; woff = 12544; local = t - 12544; }
        else return;
        int c = local / O, o = local % O;
        float wa = 0.f, wb = 0.f;
        if (c < C) {
            wa = W[o * (2 * C) + c];
            wb = W[o * (2 * C) + C + c];
        }
        int idx = woff + (c >> 1) * 2 * O + 2 * o + (c & 1);
        g_wa[idx] = wa;
        g_wu[idx] = wb - wa;
    }
}

// -------- neg pairwise distance Gram GEMM: symmetric, 128x128 tile, 8x8, f32x2 --------
__global__ __launch_bounds__(256, 2) void kd_kernel(int src, int off, int stride, int C) {
    __shared__ __align__(16) float Ad[16 * 260];
    __shared__ __align__(16) float Bs_[16 * 132];
    int b = blockIdx.z;
    int bi = 0, rem = blockIdx.x;
    while (rem >= 8 - bi) { rem -= 8 - bi; bi++; }
    int bj = bi + rem;
    int ib = bi * 128, jb = bj * 128;
    int tid = threadIdx.x;
    int tx = tid & 15, ty = tid >> 4;
    const float* fb = featPtr(src, off) + (size_t)b * NN * stride;

    ull acc[8][4];
#pragma unroll
    for (int i = 0; i < 8; i++)
#pragma unroll
        for (int j = 0; j < 4; j++) acc[i][j] = 0ull;

    int nch = (C + 15) >> 4;
    for (int cc = 0; cc < nch; cc++) {
#pragma unroll
        for (int l0 = 0; l0 < 8; l0++) {
            int l = l0 * 256 + tid;
            int c = l & 15, r = l >> 4;
            int cg = (cc << 4) + c;
            float a = 0.f, bv = 0.f;
            if (cg < C) {
                a = fb[(size_t)(ib + r) * stride + cg];
                bv = fb[(size_t)(jb + r) * stride + cg];
            }
            *(ull*)&Ad[c * 260 + 2 * r] = bcast2(a);
            Bs_[c * 132 + r] = bv;
        }
        __syncthreads();
#pragma unroll
        for (int c = 0; c < 16; c++) {
            const float4* arow = (const float4*)&Ad[c * 260 + ty * 16];
            const float4* brow = (const float4*)&Bs_[c * 132 + tx * 8];
            float4 bq0 = brow[0];
            float4 bq1 = brow[1];
            ull b0 = *(ull*)&bq0.x, b1 = *(ull*)&bq0.z;
            ull b2 = *(ull*)&bq1.x, b3 = *(ull*)&bq1.z;
#pragma unroll
            for (int iq = 0; iq < 4; iq++) {
                float4 aq = arow[iq];
                ull a0 = *(ull*)&aq.x;
                ull a1 = *(ull*)&aq.z;
                int i0 = 2 * iq, i1 = 2 * iq + 1;
                acc[i0][0] = ffma2(a0, b0, acc[i0][0]);
                acc[i0][1] = ffma2(a0, b1, acc[i0][1]);
                acc[i0][2] = ffma2(a0, b2, acc[i0][2]);
                acc[i0][3] = ffma2(a0, b3, acc[i0][3]);
                acc[i1][0] = ffma2(a1, b0, acc[i1][0]);
                acc[i1][1] = ffma2(a1, b1, acc[i1][1]);
                acc[i1][2] = ffma2(a1, b2, acc[i1][2]);
                acc[i1][3] = ffma2(a1, b3, acc[i1][3]);
            }
        }
        __syncthreads();
    }

    const float* xxb = g_xx + b * NN;
    float xm[8], xn[8];
#pragma unroll
    for (int j = 0; j < 8; j++) xm[j] = xxb[jb + tx * 8 + j];
#pragma unroll
    for (int i = 0; i < 8; i++) xn[i] = xxb[ib + ty * 8 + i];
    float* nd = g_nd + (size_t)b * NN * NN;

#pragma unroll
    for (int i = 0; i < 8; i++) {
        float v[8];
#pragma unroll
        for (int j = 0; j < 4; j++) unpack2(acc[i][j], v[2 * j], v[2 * j + 1]);
        float4 o0, o1;
        o0.x = 2.f * v[0] - xn[i] - xm[0];
        o0.y = 2.f * v[1] - xn[i] - xm[1];
        o0.z = 2.f * v[2] - xn[i] - xm[2];
        o0.w = 2.f * v[3] - xn[i] - xm[3];
        o1.x = 2.f * v[4] - xn[i] - xm[4];
        o1.y = 2.f * v[5] - xn[i] - xm[5];
        o1.z = 2.f * v[6] - xn[i] - xm[6];
        o1.w = 2.f * v[7] - xn[i] - xm[7];
        float4* dst = (float4*)(nd + (size_t)(ib + ty * 8 + i) * NN + jb + tx * 8);
        dst[0] = o0;
        dst[1] = o1;
    }
    if (bi != bj) {
#pragma unroll
        for (int j = 0; j < 8; j++) {
            float tmp[8];
#pragma unroll
            for (int i = 0; i < 8; i++) {
                float lo, hi;
                unpack2(acc[i][j >> 1], lo, hi);
                float mv = (j & 1) ? hi : lo;
                tmp[i] = 2.f * mv - xn[i] - xm[j];
            }
            float4* d2 = (float4*)(nd + (size_t)(jb + tx * 8 + j) * NN + ib + ty * 8);
            d2[0] = make_float4(tmp[0], tmp[1], tmp[2], tmp[3]);
            d2[1] = make_float4(tmp[4], tmp[5], tmp[6], tmp[7]);
        }
    }
}

__device__ __forceinline__ ull packkey(float v, int gidx) {
    unsigned bb = __float_as_uint(v);
    bb ^= (unsigned)(((int)bb >> 31)) | 0x80000000u;
    return ((ull)bb << 32) | (ull)(1023 - gidx);
}

// -------- fused: top-20 (blocks 0..1023) + v/u GEMM f32x2 (rest) --------
__global__ __launch_bounds__(256, 4) void tk2_kernel(int src, int off, int stride,
                                                     int C, int CP, int O, int och, int woff) {
    __shared__ __align__(8) float sf[16 * 128];
    if (blockIdx.x < 1024) {
        int wid = threadIdx.x >> 5;
        int lane = threadIdx.x & 31;
        int rowg = blockIdx.x * 8 + wid;
        const float* row = g_nd + (size_t)rowg * NN;

        float vals[32];
#pragma unroll
        for (int j = 0; j < 32; j++) vals[j] = row[j * 32 + lane];

        unsigned alive = 0xffffffffu;
        float qv0, qv1, qv2, qv3;
        int qj0, qj1, qj2, qj3;

#define RESCANQ(Q, QV, QJ)                                            \
        {                                                             \
            QV = -3.0e38f; QJ = (Q) * 8;                              \
            _Pragma("unroll")                                         \
            for (int j0 = 0; j0 < 8; j0++) {                          \
                int j = (Q) * 8 + j0;                                 \
                float v = ((alive >> j) & 1u) ? vals[j] : -3.0e38f;   \
                if (v > QV) { QV = v; QJ = j; }                       \
            }                                                         \
        }

        RESCANQ(0, qv0, qj0)
        RESCANQ(1, qv1, qj1)
        RESCANQ(2, qv2, qj2)
        RESCANQ(3, qv3, qj3)

        float lv = qv0; int li = qj0;
        if (qv1 > lv) { lv = qv1; li = qj1; }
        if (qv2 > lv) { lv = qv2; li = qj2; }
        if (qv3 > lv) { lv = qv3; li = qj3; }

        int myout = 0;
        for (int k = 0; k < KK; k++) {
            ull key = packkey(lv, li * 32 + lane);
#pragma unroll
            for (int s = 16; s; s >>= 1) {
                ull ok = __shfl_xor_sync(0xffffffffu, key, s);
                key = (ok > key) ? ok : key;
            }
            int gidx = 1023 - (int)(key & 0xffffffffu);
            if (lane == k) myout = gidx;
            if (lane == (gidx & 31)) {
                int jrem = gidx >> 5;
                alive &= ~(1u << jrem);
                int q = jrem >> 3;
                if (q == 0)      RESCANQ(0, qv0, qj0)
                else if (q == 1) RESCANQ(1, qv1, qj1)
                else if (q == 2) RESCANQ(2, qv2, qj2)
                else             RESCANQ(3, qv3, qj3)
                lv = qv0; li = qj0;
                if (qv1 > lv) { lv = qv1; li = qj1; }
                if (qv2 > lv) { lv = qv2; li = qj2; }
                if (qv3 > lv) { lv = qv3; li = qj3; }
            }
        }
        if (lane < KK) g_idx[rowg * KK + lane] = myout;
#undef RESCANQ
    } else {
        int kb = blockIdx.x - 1024;
        int bpb = 64 * och;
        int b = kb / bpb;
        int rm = kb % bpb;
        int n0 = (rm / och) * 16;
        int o0 = (rm % och) * 64;
        int og = threadIdx.x & 63;
        int pg = threadIdx.x >> 6;
        int o = o0 + og;
        const float* fb = featPtr(src, off) + ((size_t)b * NN + n0) * stride;
        for (int l = threadIdx.x; l < 16 * CP; l += 256) {
            int p = l / CP, c = l % CP;
            sf[p * CP + c] = (c < C) ? fb[(size_t)p * stride + c] : 0.f;
        }
        __syncthreads();
        ull va2[4], vu2[4];
#pragma unroll
        for (int p = 0; p < 4; p++) { va2[p] = 0ull; vu2[p] = 0ull; }
        const ull* wap = (const ull*)(g_wa + woff + 2 * o);
        const ull* wup = (const ull*)(g_wu + woff + 2 * o);
        int nhp = CP >> 1;
        const ull* sfp = (const ull*)sf + pg * 4 * nhp;
        for (int cp = 0; cp < nhp; cp++) {
            ull w2a = wap[cp * O];
            ull w2u = wup[cp * O];
#pragma unroll
            for (int p = 0; p < 4; p++) {
                ull f2 = sfp[p * nhp + cp];
                va2[p] = ffma2(w2a, f2, va2[p]);
                vu2[p] = ffma2(w2u, f2, vu2[p]);
            }
        }
#pragma unroll
        for (int p = 0; p < 4; p++) {
            float lo, hi;
            unpack2(va2[p], lo, hi);
            float va = lo + hi;
            unpack2(vu2[p], lo, hi);
            float vu = lo + hi;
            size_t idx = ((size_t)b * NN + n0 + pg * 4 + p) * O + o;
            g_v[idx] = va;
            g_u[idx] = vu;
        }
    }
}

// -------- gather + k-reduce + channel stats + folded BN finalize --------
__global__ __launch_bounds__(256, 8) void k3_kernel(const float* __restrict__ gam,
                          const float* __restrict__ bet, int O, int total_blocks) {
    int b = blockIdx.y;
    int n0 = blockIdx.x * 16;
    int o = threadIdx.x % O;
    int pp = threadIdx.x / O;
    int ppl = 256 / O;
    int ppp = 16 / ppl;
    size_t base = (size_t)b * NN;
    float s = 0.f, q = 0.f;
    for (int p = 0; p < ppp; p++) {
        int n = n0 + pp * ppp + p;
        const int* id = g_idx + (base + n) * KK;
        float uu = g_u[(base + n) * O + o];
        float mx = -3.0e38f, mn = 3.0e38f;
#pragma unroll
        for (int k = 0; k < KK; k++) {
            int j = id[k];
            float y = g_v[(base + j) * O + o] + uu;
            mx = fmaxf(mx, y);
            mn = fminf(mn, y);
            s += y;
            q = fmaf(y, y, q);
        }
        size_t t = (base + n) * O + o;
        g_maxv[t] = mx;
        g_minv[t] = mn;
    }
    atomicAdd(&g_sum[o], s);
    atomicAdd(&g_sq[o], q);

    // ALL block writes complete before signalling done (bar.sync makes them
    // block-visible; thread 0's fence then releases them chip-wide).
    __syncthreads();
    __threadfence();
    __shared__ int isLast;
    if (threadIdx.x == 0) isLast = (atomicAdd(&g_cnt, 1) == total_blocks - 1);
    __syncthreads();
    if (isLast && threadIdx.x < O) {
        volatile float* vs = g_sum;
        volatile float* vq = g_sq;
        float cnt = (float)(BB * NN * KK);
        float m = vs[o] / cnt;
        float var = vq[o] / cnt - m * m;
        float sc = gam[o] * rsqrtf(var + 1e-5f);
        g_scale[o] = sc;
        g_bias[o] = bet[o] - m * sc;
        if (o == 0) g_cnt = 0;
    }
}

// -------- BN+lrelu apply -> cat ; fused next-layer xx ; zero stats --------
__global__ void k4b(int O, int coff, int do_xx) {
    __shared__ float sq_s[8];
    if (blockIdx.x == 0) {
        for (int z = threadIdx.x; z < O5; z += 256) { g_sum[z] = 0.f; g_sq[z] = 0.f; }
    }
    int t = blockIdx.x * 256 + threadIdx.x;
    int o = t % O;
    size_t pn = t / O;
    float sc = g_scale[o], bi = g_bias[o];
    float sel = (sc >= 0.f) ? g_maxv[t] : g_minv[t];
    float y = fmaf(sc, sel, bi);
    float act = (y >= 0.f) ? y : 0.2f * y;
    g_cat[pn * CAT + coff + o] = act;
    if (do_xx) {
        float q = act * act;
#pragma unroll
        for (int s = 16; s; s >>= 1) q += __shfl_xor_sync(0xffffffffu, q, s);
        if ((threadIdx.x & 31) == 0) sq_s[threadIdx.x >> 5] = q;
        __syncthreads();
        int pts = 256 / O, wpp = O / 32;
        if (threadIdx.x < pts) {
            float a = 0.f;
            for (int w = 0; w < wpp; w++) a += sq_s[threadIdx.x * wpp + w];
            g_xx[(size_t)blockIdx.x * pts + threadIdx.x] = a;
        }
    }
}

// -------- final conv1d GEMM + fused n-stats + last-block final BN/lrelu/max --------
__global__ __launch_bounds__(256, 2) void f1_kernel(const float* __restrict__ W5,
                                                    const float* __restrict__ g5,
                                                    const float* __restrict__ b5,
                                                    float* __restrict__ out) {
    __shared__ __align__(16) float Ad[16 * 260];
    __shared__ __align__(16) float Bs_[16 * 132];
    int ob = blockIdx.x * 128;
    int nb = blockIdx.y * 128;
    int b = blockIdx.z;
    int tid = threadIdx.x;
    int tx = tid & 15, ty = tid >> 4;
    const float* cb = g_cat + (size_t)b * NN * CAT;

    ull acc[8][4];
#pragma unroll
    for (int i = 0; i < 8; i++)
#pragma unroll
        for (int j = 0; j < 4; j++) acc[i][j] = 0ull;

    for (int cc = 0; cc < 32; cc++) {
#pragma unroll
        for (int l0 = 0; l0 < 8; l0++) {
            int l = l0 * 256 + tid;
            int c = l & 15, r = l >> 4;
            float a = W5[(size_t)(ob + r) * 512 + (cc << 4) + c];
            float bv = cb[(size_t)(nb + r) * 512 + (cc << 4) + c];
            *(ull*)&Ad[c * 260 + 2 * r] = bcast2(a);
            Bs_[c * 132 + r] = bv;
        }
        __syncthreads();
#pragma unroll
        for (int c = 0; c < 16; c++) {
            const float4* arow = (const float4*)&Ad[c * 260 + ty * 16];
            const float4* brow = (const float4*)&Bs_[c * 132 + tx * 8];
            float4 bq0 = brow[0];
            float4 bq1 = brow[1];
            ull b0 = *(ull*)&bq0.x, b1 = *(ull*)&bq0.z;
            ull b2 = *(ull*)&bq1.x, b3 = *(ull*)&bq1.z;
#pragma unroll
            for (int iq = 0; iq < 4; iq++) {
                float4 aq = arow[iq];
                ull a0 = *(ull*)&aq.x;
                ull a1 = *(ull*)&aq.z;
                int i0 = 2 * iq, i1 = 2 * iq + 1;
                acc[i0][0] = ffma2(a0, b0, acc[i0][0]);
                acc[i0][1] = ffma2(a0, b1, acc[i0][1]);
                acc[i0][2] = ffma2(a0, b2, acc[i0][2]);
                acc[i0][3] = ffma2(a0, b3, acc[i0][3]);
                acc[i1][0] = ffma2(a1, b0, acc[i1][0]);
                acc[i1][1] = ffma2(a1, b1, acc[i1][1]);
                acc[i1][2] = ffma2(a1, b2, acc[i1][2]);
                acc[i1][3] = ffma2(a1, b3, acc[i1][3]);
            }
        }
        __syncthreads();
    }

#pragma unroll
    for (int i = 0; i < 8; i++) {
        float v[8];
#pragma unroll
        for (int j = 0; j < 4; j++) unpack2(acc[i][j], v[2 * j], v[2 * j + 1]);
        float mx = v[0], mn = v[0], s = v[0], q = v[0] * v[0];
#pragma unroll
        for (int j = 1; j < 8; j++) {
            mx = fmaxf(mx, v[j]);
            mn = fminf(mn, v[j]);
            s += v[j];
            q = fmaf(v[j], v[j], q);
        }
#pragma unroll
        for (int st = 8; st; st >>= 1) {
            mx = fmaxf(mx, __shfl_xor_sync(0xffffffffu, mx, st));
            mn = fminf(mn, __shfl_xor_sync(0xffffffffu, mn, st));
            s += __shfl_xor_sync(0xffffffffu, s, st);
            q += __shfl_xor_sync(0xffffffffu, q, st);
        }
        if (tx == 0) {
            int o = ob + ty * 8 + i;
            g_pmax[((size_t)b * O5 + o) * 8 + blockIdx.y] = mx;
            g_pmin[((size_t)b * O5 + o) * 8 + blockIdx.y] = mn;
            atomicAdd(&g_sum[o], s);
            atomicAdd(&g_sq[o], q);
        }
    }

    // last-block: final BN + lrelu + max over n (replaces f2 launch).
    // __syncthreads BEFORE the fence: all threads' pmax/pmin stores and stat
    // atomics must be complete before this block signals done.
    __syncthreads();
    __threadfence();
    __shared__ int isLast;
    if (tid == 0) isLast = (atomicAdd(&g_cnt, 1) == 511);
    __syncthreads();
    if (isLast) {
        volatile float* vs = g_sum;
        volatile float* vq = g_sq;
        for (int t = tid; t < BB * O5; t += 256) {
            int bb2 = t / O5, o = t % O5;
            float m = vs[o] / 8192.f;
            float var = vq[o] / 8192.f - m * m;
            float sc = g5[o] * rsqrtf(var + 1e-5f);
            float bi = b5[o] - m * sc;
            volatile float* pm = (sc >= 0.f) ? g_pmax : g_pmin;
            size_t base = ((size_t)bb2 * O5 + o) * 8;
            float sel = pm[base];
            if (sc >= 0.f) {
                for (int i = 1; i < 8; i++) sel = fmaxf(sel, pm[base + i]);
            } else {
                for (int i = 1; i < 8; i++) sel = fminf(sel, pm[base + i]);
            }
            float y = fmaf(sc, sel, bi);
            out[t] = (y >= 0.f) ? y : 0.2f * y;
        }
        if (tid == 0) g_cnt = 0;
    }
}

extern "C" void kernel_launch(void* const* d_in, const int* in_sizes, int n_in,
                              void* d_out, int out_size) {
    const float* x  = (const float*)d_in[0];
    const float* Wl[4] = {(const float*)d_in[1], (const float*)d_in[4],
                          (const float*)d_in[7], (const float*)d_in[10]};
    const float* gl[4] = {(const float*)d_in[2], (const float*)d_in[5],
                          (const float*)d_in[8], (const float*)d_in[11]};
    const float* bl[4] = {(const float*)d_in[3], (const float*)d_in[6],
                          (const float*)d_in[9], (const float*)d_in[12]};
    const float* W5 = (const float*)d_in[13];
    const float* g5 = (const float*)d_in[14];
    const float* b5 = (const float*)d_in[15];
    float* out = (float*)d_out;

    prep0<<<210, 256>>>(x, Wl[0], Wl[1], Wl[2], Wl[3]);

    const int srcA[4]  = {0, 1, 1, 1};
    const int offA[4]  = {0, 0, 64, 128};
    const int CA[4]    = {3, 64, 64, 128};
    const int CPA[4]   = {4, 64, 64, 128};
    const int OA[4]    = {64, 64, 128, 256};
    const int coffA[4] = {0, 64, 128, 256};
    const int woffA[4] = {0, 256, 4352, 12544};

    for (int L = 0; L < 4; L++) {
        int src = srcA[L], off = offA[L], C = CA[L], CP = CPA[L], O = OA[L];
        int coff = coffA[L], woff = woffA[L];
        int stride = src ? CAT : 4;
        int och = O / 64;
        kd_kernel<<<dim3(36, 1, BB), 256>>>(src, off, stride, C);
        tk2_kernel<<<1024 + 512 * och, 256>>>(src, off, stride, C, CP, O, och, woff);
        k3_kernel<<<dim3(64, BB), 256>>>(gl[L], bl[L], O, 512);
        k4b<<<BB * NN * O / 256, 256>>>(O, coff, (L < 3) ? 1 : 0);
    }

    f1_kernel<<<dim3(8, 8, BB), 256>>>(W5, g5, b5, out);
}

// round 12
// speedup vs baseline: 1.7536x; 1.0298x over previous
#include <cuda_runtime.h>

#define BB 8
#define NN 1024
#define KK 20
#define CAT 512
#define O5 1024

typedef unsigned long long ull;

__device__ __forceinline__ ull ffma2(ull a, ull b, ull c) {
    ull d;
    asm("fma.rn.f32x2 %0, %1, %2, %3;" : "=l"(d) : "l"(a), "l"(b), "l"(c));
    return d;
}
__device__ __forceinline__ ull bcast2(float v) {
    ull d;
    asm("mov.b64 %0, {%1, %1};" : "=l"(d) : "f"(v));
    return d;
}
__device__ __forceinline__ void unpack2(ull p, float& lo, float& hi) {
    asm("mov.b64 {%0, %1}, %2;" : "=f"(lo), "=f"(hi) : "l"(p));
}

// -------- static device workspaces --------
__device__ __align__(16) float g_f0[BB * NN * 4];
__device__ __align__(16) float g_cat[BB * NN * CAT];
__device__ float g_xx[BB * NN];
__device__ float g_nd[BB * NN * NN];
__device__ int   g_idx[BB * NN * KK];
__device__ float g_v[BB * NN * 256];
__device__ float g_u[BB * NN * 256];
__device__ __align__(8) float g_wa[64 * 1024];   // packed: pair-major {w[c],w[c+1]}
__device__ __align__(8) float g_wu[64 * 1024];
__device__ float g_maxv[BB * NN * 256];
__device__ float g_minv[BB * NN * 256];
__device__ float g_sum[O5];
__device__ float g_sq[O5];
__device__ float g_pmax[BB * O5 * 8];
__device__ float g_pmin[BB * O5 * 8];
__device__ float g_scale[256];
__device__ float g_bias[256];
__device__ int   g_cnt;

__device__ __forceinline__ const float* featPtr(int src, int off) {
    return src ? (g_cat + off) : g_f0;
}

// -------- fused prep: transpose x + xx(layer1) + ALL W splits (pair-packed) + zero stats --------
__global__ void prep0(const float* __restrict__ x,
                      const float* __restrict__ W1, const float* __restrict__ W2,
                      const float* __restrict__ W3, const float* __restrict__ W4) {
    int bx = blockIdx.x;
    if (bx < 32) {
        int t = bx * 256 + threadIdx.x;
        int b = t / NN, n = t % NN;
        float x0 = x[(b * 3 + 0) * NN + n];
        float x1 = x[(b * 3 + 1) * NN + n];
        float x2 = x[(b * 3 + 2) * NN + n];
        float* d = g_f0 + (size_t)t * 4;
        d[0] = x0; d[1] = x1; d[2] = x2; d[3] = 0.f;
        float a = fmaf(x0, x0, 0.f);
        a = fmaf(x1, x1, a);
        a = fmaf(x2, x2, a);
        g_xx[t] = a;
    } else if (bx == 32) {
        for (int t = threadIdx.x; t < O5; t += 256) { g_sum[t] = 0.f; g_sq[t] = 0.f; }
    } else {
        int t = (bx - 33) * 256 + threadIdx.x;
        const float* W; int C, O, woff, local;
        if (t < 256)        { W = W1; C = 3;   O = 64;  woff = 0;     local = t; }          // CP=4
        else if (t < 4352)  { W = W2; C = 64;  O = 64;  woff = 256;   local = t - 256; }
        else if (t < 12544) { W = W3; C = 64;  O = 128; woff = 4352;  local = t - 4352; }
        else if (t < 45312) { W = W4; C = 128; O = 256; woff = 12544; local = t - 12544; }
        else return;
        int c = local / O, o = local % O;
        float wa = 0.f, wb = 0.f;
        if (c < C) {
            wa = W[o * (2 * C) + c];
            wb = W[o * (2 * C) + C + c];
        }
        int idx = woff + (c >> 1) * 2 * O + 2 * o + (c & 1);
        g_wa[idx] = wa;
        g_wu[idx] = wb - wa;
    }
}

// -------- neg pairwise distance Gram GEMM: symmetric, 128x128 tile, 8x8, f32x2 --------
// Fill phase: 2+2 LDG.128 per thread per chunk (was 16 scalar LDG).
__global__ __launch_bounds__(256, 2) void kd_kernel(int src, int off, int stride, int C) {
    __shared__ __align__(16) float Ad[16 * 260];
    __shared__ __align__(16) float Bs_[16 * 132];
    int b = blockIdx.z;
    int bi = 0, rem = blockIdx.x;
    while (rem >= 8 - bi) { rem -= 8 - bi; bi++; }
    int bj = bi + rem;
    int ib = bi * 128, jb = bj * 128;
    int tid = threadIdx.x;
    int tx = tid & 15, ty = tid >> 4;
    const float* fb = featPtr(src, off) + (size_t)b * NN * stride;

    ull acc[8][4];
#pragma unroll
    for (int i = 0; i < 8; i++)
#pragma unroll
        for (int j = 0; j < 4; j++) acc[i][j] = 0ull;

    int nch = (C + 15) >> 4;
    for (int cc = 0; cc < nch; cc++) {
#pragma unroll
        for (int h = 0; h < 2; h++) {
            int f4i = h * 256 + tid;       // 0..511
            int r = f4i >> 2;              // 0..127
            int cq = f4i & 3;
            int cg0 = (cc << 4) + cq * 4;
            float4 av, bv;
            if (cg0 < C) {
                av = *(const float4*)&fb[(size_t)(ib + r) * stride + cg0];
                bv = *(const float4*)&fb[(size_t)(jb + r) * stride + cg0];
            } else {
                av = make_float4(0.f, 0.f, 0.f, 0.f);
                bv = av;
            }
            int cb_ = cq * 4;
            *(ull*)&Ad[(cb_ + 0) * 260 + 2 * r] = bcast2(av.x);
            *(ull*)&Ad[(cb_ + 1) * 260 + 2 * r] = bcast2(av.y);
            *(ull*)&Ad[(cb_ + 2) * 260 + 2 * r] = bcast2(av.z);
            *(ull*)&Ad[(cb_ + 3) * 260 + 2 * r] = bcast2(av.w);
            Bs_[(cb_ + 0) * 132 + r] = bv.x;
            Bs_[(cb_ + 1) * 132 + r] = bv.y;
            Bs_[(cb_ + 2) * 132 + r] = bv.z;
            Bs_[(cb_ + 3) * 132 + r] = bv.w;
        }
        __syncthreads();
#pragma unroll
        for (int c = 0; c < 16; c++) {
            const float4* arow = (const float4*)&Ad[c * 260 + ty * 16];
            const float4* brow = (const float4*)&Bs_[c * 132 + tx * 8];
            float4 bq0 = brow[0];
            float4 bq1 = brow[1];
            ull b0 = *(ull*)&bq0.x, b1 = *(ull*)&bq0.z;
            ull b2 = *(ull*)&bq1.x, b3 = *(ull*)&bq1.z;
#pragma unroll
            for (int iq = 0; iq < 4; iq++) {
                float4 aq = arow[iq];
                ull a0 = *(ull*)&aq.x;
                ull a1 = *(ull*)&aq.z;
                int i0 = 2 * iq, i1 = 2 * iq + 1;
                acc[i0][0] = ffma2(a0, b0, acc[i0][0]);
                acc[i0][1] = ffma2(a0, b1, acc[i0][1]);
                acc[i0][2] = ffma2(a0, b2, acc[i0][2]);
                acc[i0][3] = ffma2(a0, b3, acc[i0][3]);
                acc[i1][0] = ffma2(a1, b0, acc[i1][0]);
                acc[i1][1] = ffma2(a1, b1, acc[i1][1]);
                acc[i1][2] = ffma2(a1, b2, acc[i1][2]);
                acc[i1][3] = ffma2(a1, b3, acc[i1][3]);
            }
        }
        __syncthreads();
    }

    const float* xxb = g_xx + b * NN;
    float xm[8], xn[8];
#pragma unroll
    for (int j = 0; j < 8; j++) xm[j] = xxb[jb + tx * 8 + j];
#pragma unroll
    for (int i = 0; i < 8; i++) xn[i] = xxb[ib + ty * 8 + i];
    float* nd = g_nd + (size_t)b * NN * NN;

#pragma unroll
    for (int i = 0; i < 8; i++) {
        float v[8];
#pragma unroll
        for (int j = 0; j < 4; j++) unpack2(acc[i][j], v[2 * j], v[2 * j + 1]);
        float4 o0, o1;
        o0.x = 2.f * v[0] - xn[i] - xm[0];
        o0.y = 2.f * v[1] - xn[i] - xm[1];
        o0.z = 2.f * v[2] - xn[i] - xm[2];
        o0.w = 2.f * v[3] - xn[i] - xm[3];
        o1.x = 2.f * v[4] - xn[i] - xm[4];
        o1.y = 2.f * v[5] - xn[i] - xm[5];
        o1.z = 2.f * v[6] - xn[i] - xm[6];
        o1.w = 2.f * v[7] - xn[i] - xm[7];
        float4* dst = (float4*)(nd + (size_t)(ib + ty * 8 + i) * NN + jb + tx * 8);
        dst[0] = o0;
        dst[1] = o1;
    }
    if (bi != bj) {
#pragma unroll
        for (int j = 0; j < 8; j++) {
            float tmp[8];
#pragma unroll
            for (int i = 0; i < 8; i++) {
                float lo, hi;
                unpack2(acc[i][j >> 1], lo, hi);
                float mv = (j & 1) ? hi : lo;
                tmp[i] = 2.f * mv - xn[i] - xm[j];
            }
            float4* d2 = (float4*)(nd + (size_t)(jb + tx * 8 + j) * NN + ib + ty * 8);
            d2[0] = make_float4(tmp[0], tmp[1], tmp[2], tmp[3]);
            d2[1] = make_float4(tmp[4], tmp[5], tmp[6], tmp[7]);
        }
    }
}

__device__ __forceinline__ ull packkey(float v, int gidx) {
    unsigned bb = __float_as_uint(v);
    bb ^= (unsigned)(((int)bb >> 31)) | 0x80000000u;
    return ((ull)bb << 32) | (ull)(1023 - gidx);
}

// -------- fused: top-20 (blocks 0..1023) + v/u GEMM f32x2 (rest) --------
__global__ __launch_bounds__(256, 4) void tk2_kernel(int src, int off, int stride,
                                                     int C, int CP, int O, int och, int woff) {
    __shared__ __align__(8) float sf[16 * 128];
    if (blockIdx.x < 1024) {
        int wid = threadIdx.x >> 5;
        int lane = threadIdx.x & 31;
        int rowg = blockIdx.x * 8 + wid;
        const float* row = g_nd + (size_t)rowg * NN;

        float vals[32];
#pragma unroll
        for (int j = 0; j < 32; j++) vals[j] = row[j * 32 + lane];

        unsigned alive = 0xffffffffu;
        float qv0, qv1, qv2, qv3;
        int qj0, qj1, qj2, qj3;

#define RESCANQ(Q, QV, QJ)                                            \
        {                                                             \
            QV = -3.0e38f; QJ = (Q) * 8;                              \
            _Pragma("unroll")                                         \
            for (int j0 = 0; j0 < 8; j0++) {                          \
                int j = (Q) * 8 + j0;                                 \
                float v = ((alive >> j) & 1u) ? vals[j] : -3.0e38f;   \
                if (v > QV) { QV = v; QJ = j; }                       \
            }                                                         \
        }

        RESCANQ(0, qv0, qj0)
        RESCANQ(1, qv1, qj1)
        RESCANQ(2, qv2, qj2)
        RESCANQ(3, qv3, qj3)

        float lv = qv0; int li = qj0;
        if (qv1 > lv) { lv = qv1; li = qj1; }
        if (qv2 > lv) { lv = qv2; li = qj2; }
        if (qv3 > lv) { lv = qv3; li = qj3; }

        int myout = 0;
        for (int k = 0; k < KK; k++) {
            ull key = packkey(lv, li * 32 + lane);
#pragma unroll
            for (int s = 16; s; s >>= 1) {
                ull ok = __shfl_xor_sync(0xffffffffu, key, s);
                key = (ok > key) ? ok : key;
            }
            int gidx = 1023 - (int)(key & 0xffffffffu);
            if (lane == k) myout = gidx;
            if (lane == (gidx & 31)) {
                int jrem = gidx >> 5;
                alive &= ~(1u << jrem);
                int q = jrem >> 3;
                if (q == 0)      RESCANQ(0, qv0, qj0)
                else if (q == 1) RESCANQ(1, qv1, qj1)
                else if (q == 2) RESCANQ(2, qv2, qj2)
                else             RESCANQ(3, qv3, qj3)
                lv = qv0; li = qj0;
                if (qv1 > lv) { lv = qv1; li = qj1; }
                if (qv2 > lv) { lv = qv2; li = qj2; }
                if (qv3 > lv) { lv = qv3; li = qj3; }
            }
        }
        if (lane < KK) g_idx[rowg * KK + lane] = myout;
#undef RESCANQ
    } else {
        int kb = blockIdx.x - 1024;
        int bpb = 64 * och;
        int b = kb / bpb;
        int rm = kb % bpb;
        int n0 = (rm / och) * 16;
        int o0 = (rm % och) * 64;
        int og = threadIdx.x & 63;
        int pg = threadIdx.x >> 6;
        int o = o0 + og;
        const float* fb = featPtr(src, off) + ((size_t)b * NN + n0) * stride;
        for (int l = threadIdx.x; l < 16 * CP; l += 256) {
            int p = l / CP, c = l % CP;
            sf[p * CP + c] = (c < C) ? fb[(size_t)p * stride + c] : 0.f;
        }
        __syncthreads();
        ull va2[4], vu2[4];
#pragma unroll
        for (int p = 0; p < 4; p++) { va2[p] = 0ull; vu2[p] = 0ull; }
        const ull* wap = (const ull*)(g_wa + woff + 2 * o);
        const ull* wup = (const ull*)(g_wu + woff + 2 * o);
        int nhp = CP >> 1;
        const ull* sfp = (const ull*)sf + pg * 4 * nhp;
        for (int cp = 0; cp < nhp; cp++) {
            ull w2a = wap[cp * O];
            ull w2u = wup[cp * O];
#pragma unroll
            for (int p = 0; p < 4; p++) {
                ull f2 = sfp[p * nhp + cp];
                va2[p] = ffma2(w2a, f2, va2[p]);
                vu2[p] = ffma2(w2u, f2, vu2[p]);
            }
        }
#pragma unroll
        for (int p = 0; p < 4; p++) {
            float lo, hi;
            unpack2(va2[p], lo, hi);
            float va = lo + hi;
            unpack2(vu2[p], lo, hi);
            float vu = lo + hi;
            size_t idx = ((size_t)b * NN + n0 + pg * 4 + p) * O + o;
            g_v[idx] = va;
            g_u[idx] = vu;
        }
    }
}

// -------- gather + k-reduce + channel stats + folded BN finalize --------
__global__ __launch_bounds__(256, 8) void k3_kernel(const float* __restrict__ gam,
                          const float* __restrict__ bet, int O, int total_blocks) {
    int b = blockIdx.y;
    int n0 = blockIdx.x * 16;
    int o = threadIdx.x % O;
    int pp = threadIdx.x / O;
    int ppl = 256 / O;
    int ppp = 16 / ppl;
    size_t base = (size_t)b * NN;
    float s = 0.f, q = 0.f;
    for (int p = 0; p < ppp; p++) {
        int n = n0 + pp * ppp + p;
        const int* id = g_idx + (base + n) * KK;
        float uu = g_u[(base + n) * O + o];
        float mx = -3.0e38f, mn = 3.0e38f;
#pragma unroll
        for (int k = 0; k < KK; k++) {
            int j = id[k];
            float y = g_v[(base + j) * O + o] + uu;
            mx = fmaxf(mx, y);
            mn = fminf(mn, y);
            s += y;
            q = fmaf(y, y, q);
        }
        size_t t = (base + n) * O + o;
        g_maxv[t] = mx;
        g_minv[t] = mn;
    }
    atomicAdd(&g_sum[o], s);
    atomicAdd(&g_sq[o], q);

    __syncthreads();
    __threadfence();
    __shared__ int isLast;
    if (threadIdx.x == 0) isLast = (atomicAdd(&g_cnt, 1) == total_blocks - 1);
    __syncthreads();
    if (isLast && threadIdx.x < O) {
        volatile float* vs = g_sum;
        volatile float* vq = g_sq;
        float cnt = (float)(BB * NN * KK);
        float m = vs[o] / cnt;
        float var = vq[o] / cnt - m * m;
        float sc = gam[o] * rsqrtf(var + 1e-5f);
        g_scale[o] = sc;
        g_bias[o] = bet[o] - m * sc;
        if (o == 0) g_cnt = 0;
    }
}

// -------- BN+lrelu apply -> cat ; fused next-layer xx ; zero stats --------
__global__ void k4b(int O, int coff, int do_xx) {
    __shared__ float sq_s[8];
    if (blockIdx.x == 0) {
        for (int z = threadIdx.x; z < O5; z += 256) { g_sum[z] = 0.f; g_sq[z] = 0.f; }
    }
    int t = blockIdx.x * 256 + threadIdx.x;
    int o = t % O;
    size_t pn = t / O;
    float sc = g_scale[o], bi = g_bias[o];
    float sel = (sc >= 0.f) ? g_maxv[t] : g_minv[t];
    float y = fmaf(sc, sel, bi);
    float act = (y >= 0.f) ? y : 0.2f * y;
    g_cat[pn * CAT + coff + o] = act;
    if (do_xx) {
        float q = act * act;
#pragma unroll
        for (int s = 16; s; s >>= 1) q += __shfl_xor_sync(0xffffffffu, q, s);
        if ((threadIdx.x & 31) == 0) sq_s[threadIdx.x >> 5] = q;
        __syncthreads();
        int pts = 256 / O, wpp = O / 32;
        if (threadIdx.x < pts) {
            float a = 0.f;
            for (int w = 0; w < wpp; w++) a += sq_s[threadIdx.x * wpp + w];
            g_xx[(size_t)blockIdx.x * pts + threadIdx.x] = a;
        }
    }
}

// -------- final conv1d GEMM + fused n-stats + last-block final BN/lrelu/max --------
__global__ __launch_bounds__(256, 2) void f1_kernel(const float* __restrict__ W5,
                                                    const float* __restrict__ g5,
                                                    const float* __restrict__ b5,
                                                    float* __restrict__ out) {
    __shared__ __align__(16) float Ad[16 * 260];
    __shared__ __align__(16) float Bs_[16 * 132];
    int ob = blockIdx.x * 128;
    int nb = blockIdx.y * 128;
    int b = blockIdx.z;
    int tid = threadIdx.x;
    int tx = tid & 15, ty = tid >> 4;
    const float* cb = g_cat + (size_t)b * NN * CAT;

    ull acc[8][4];
#pragma unroll
    for (int i = 0; i < 8; i++)
#pragma unroll
        for (int j = 0; j < 4; j++) acc[i][j] = 0ull;

    for (int cc = 0; cc < 32; cc++) {
#pragma unroll
        for (int h = 0; h < 2; h++) {
            int f4i = h * 256 + tid;
            int r = f4i >> 2;
            int cq = f4i & 3;
            int cg0 = (cc << 4) + cq * 4;
            float4 av = *(const float4*)&W5[(size_t)(ob + r) * 512 + cg0];
            float4 bv = *(const float4*)&cb[(size_t)(nb + r) * 512 + cg0];
            int cb_ = cq * 4;
            *(ull*)&Ad[(cb_ + 0) * 260 + 2 * r] = bcast2(av.x);
            *(ull*)&Ad[(cb_ + 1) * 260 + 2 * r] = bcast2(av.y);
            *(ull*)&Ad[(cb_ + 2) * 260 + 2 * r] = bcast2(av.z);
            *(ull*)&Ad[(cb_ + 3) * 260 + 2 * r] = bcast2(av.w);
            Bs_[(cb_ + 0) * 132 + r] = bv.x;
            Bs_[(cb_ + 1) * 132 + r] = bv.y;
            Bs_[(cb_ + 2) * 132 + r] = bv.z;
            Bs_[(cb_ + 3) * 132 + r] = bv.w;
        }
        __syncthreads();
#pragma unroll
        for (int c = 0; c < 16; c++) {
            const float4* arow = (const float4*)&Ad[c * 260 + ty * 16];
            const float4* brow = (const float4*)&Bs_[c * 132 + tx * 8];
            float4 bq0 = brow[0];
            float4 bq1 = brow[1];
            ull b0 = *(ull*)&bq0.x, b1 = *(ull*)&bq0.z;
            ull b2 = *(ull*)&bq1.x, b3 = *(ull*)&bq1.z;
#pragma unroll
            for (int iq = 0; iq < 4; iq++) {
                float4 aq = arow[iq];
                ull a0 = *(ull*)&aq.x;
                ull a1 = *(ull*)&aq.z;
                int i0 = 2 * iq, i1 = 2 * iq + 1;
                acc[i0][0] = ffma2(a0, b0, acc[i0][0]);
                acc[i0][1] = ffma2(a0, b1, acc[i0][1]);
                acc[i0][2] = ffma2(a0, b2, acc[i0][2]);
                acc[i0][3] = ffma2(a0, b3, acc[i0][3]);
                acc[i1][0] = ffma2(a1, b0, acc[i1][0]);
                acc[i1][1] = ffma2(a1, b1, acc[i1][1]);
                acc[i1][2] = ffma2(a1, b2, acc[i1][2]);
                acc[i1][3] = ffma2(a1, b3, acc[i1][3]);
            }
        }
        __syncthreads();
    }

#pragma unroll
    for (int i = 0; i < 8; i++) {
        float v[8];
#pragma unroll
        for (int j = 0; j < 4; j++) unpack2(acc[i][j], v[2 * j], v[2 * j + 1]);
        float mx = v[0], mn = v[0], s = v[0], q = v[0] * v[0];
#pragma unroll
        for (int j = 1; j < 8; j++) {
            mx = fmaxf(mx, v[j]);
            mn = fminf(mn, v[j]);
            s += v[j];
            q = fmaf(v[j], v[j], q);
        }
#pragma unroll
        for (int st = 8; st; st >>= 1) {
            mx = fmaxf(mx, __shfl_xor_sync(0xffffffffu, mx, st));
            mn = fminf(mn, __shfl_xor_sync(0xffffffffu, mn, st));
            s += __shfl_xor_sync(0xffffffffu, s, st);
            q += __shfl_xor_sync(0xffffffffu, q, st);
        }
        if (tx == 0) {
            int o = ob + ty * 8 + i;
            g_pmax[((size_t)b * O5 + o) * 8 + blockIdx.y] = mx;
            g_pmin[((size_t)b * O5 + o) * 8 + blockIdx.y] = mn;
            atomicAdd(&g_sum[o], s);
            atomicAdd(&g_sq[o], q);
        }
    }

    __syncthreads();
    __threadfence();
    __shared__ int isLast;
    if (tid == 0) isLast = (atomicAdd(&g_cnt, 1) == 511);
    __syncthreads();
    if (isLast) {
        volatile float* vs = g_sum;
        volatile float* vq = g_sq;
        for (int t = tid; t < BB * O5; t += 256) {
            int bb2 = t / O5, o = t % O5;
            float m = vs[o] / 8192.f;
            float var = vq[o] / 8192.f - m * m;
            float sc = g5[o] * rsqrtf(var + 1e-5f);
            float bi = b5[o] - m * sc;
            volatile float* pm = (sc >= 0.f) ? g_pmax : g_pmin;
            size_t base = ((size_t)bb2 * O5 + o) * 8;
            float sel = pm[base];
            if (sc >= 0.f) {
                for (int i = 1; i < 8; i++) sel = fmaxf(sel, pm[base + i]);
            } else {
                for (int i = 1; i < 8; i++) sel = fminf(sel, pm[base + i]);
            }
            float y = fmaf(sc, sel, bi);
            out[t] = (y >= 0.f) ? y : 0.2f * y;
        }
        if (tid == 0) g_cnt = 0;
    }
}

extern "C" void kernel_launch(void* const* d_in, const int* in_sizes, int n_in,
                              void* d_out, int out_size) {
    const float* x  = (const float*)d_in[0];
    const float* Wl[4] = {(const float*)d_in[1], (const float*)d_in[4],
                          (const float*)d_in[7], (const float*)d_in[10]};
    const float* gl[4] = {(const float*)d_in[2], (const float*)d_in[5],
                          (const float*)d_in[8], (const float*)d_in[11]};
    const float* bl[4] = {(const float*)d_in[3], (const float*)d_in[6],
                          (const float*)d_in[9], (const float*)d_in[12]};
    const float* W5 = (const float*)d_in[13];
    const float* g5 = (const float*)d_in[14];
    const float* b5 = (const float*)d_in[15];
    float* out = (float*)d_out;

    prep0<<<210, 256>>>(x, Wl[0], Wl[1], Wl[2], Wl[3]);

    const int srcA[4]  = {0, 1, 1, 1};
    const int offA[4]  = {0, 0, 64, 128};
    const int CA[4]    = {3, 64, 64, 128};
    const int CPA[4]   = {4, 64, 64, 128};
    const int OA[4]    = {64, 64, 128, 256};
    const int coffA[4] = {0, 64, 128, 256};
    const int woffA[4] = {0, 256, 4352, 12544};

    for (int L = 0; L < 4; L++) {
        int src = srcA[L], off = offA[L], C = CA[L], CP = CPA[L], O = OA[L];
        int coff = coffA[L], woff = woffA[L];
        int stride = src ? CAT : 4;
        int och = O / 64;
        kd_kernel<<<dim3(36, 1, BB), 256>>>(src, off, stride, C);
        tk2_kernel<<<1024 + 512 * och, 256>>>(src, off, stride, C, CP, O, och, woff);
        k3_kernel<<<dim3(64, BB), 256>>>(gl[L], bl[L], O, 512);
        k4b<<<BB * NN * O / 256, 256>>>(O, coff, (L < 3) ? 1 : 0);
    }

    f1_kernel<<<dim3(8, 8, BB), 256>>>(W5, g5, b5, out);
}

// round 14
// speedup vs baseline: 1.7799x; 1.0150x over previous
#include <cuda_runtime.h>

#define BB 8
#define NN 1024
#define KK 20
#define CAT 512
#define O5 1024

typedef unsigned long long ull;

__device__ __forceinline__ ull ffma2(ull a, ull b, ull c) {
    ull d;
    asm("fma.rn.f32x2 %0, %1, %2, %3;" : "=l"(d) : "l"(a), "l"(b), "l"(c));
    return d;
}
__device__ __forceinline__ ull bcast2(float v) {
    ull d;
    asm("mov.b64 %0, {%1, %1};" : "=l"(d) : "f"(v));
    return d;
}
__device__ __forceinline__ void unpack2(ull p, float& lo, float& hi) {
    asm("mov.b64 {%0, %1}, %2;" : "=f"(lo), "=f"(hi) : "l"(p));
}

// -------- static device workspaces --------
__device__ __align__(16) float g_f0[BB * NN * 4];
__device__ __align__(16) float g_cat[BB * NN * CAT];
__device__ float g_xx[BB * NN];
__device__ float g_nd[BB * NN * NN];
__device__ int   g_idx[BB * NN * KK];
__device__ float g_v[BB * NN * 256];
__device__ float g_u[BB * NN * 256];
__device__ __align__(8) float g_wa[64 * 1024];   // packed: pair-major {w[c],w[c+1]}
__device__ __align__(8) float g_wu[64 * 1024];
__device__ float g_sum[O5];
__device__ float g_sq[O5];
__device__ float g_pmax[BB * O5 * 8];
__device__ float g_pmin[BB * O5 * 8];
__device__ float g_scale[256];
__device__ float g_bias[256];
__device__ int   g_cnt;
__device__ int   g_cnt2;
__device__ int   g_flag;

__device__ __forceinline__ const float* featPtr(int src, int off) {
    return src ? (g_cat + off) : g_f0;
}

// -------- fused prep: transpose x + xx(layer1) + ALL W splits (pair-packed) + zero stats --------
__global__ void prep0(const float* __restrict__ x,
                      const float* __restrict__ W1, const float* __restrict__ W2,
                      const float* __restrict__ W3, const float* __restrict__ W4) {
    int bx = blockIdx.x;
    if (bx < 32) {
        int t = bx * 256 + threadIdx.x;
        int b = t / NN, n = t % NN;
        float x0 = x[(b * 3 + 0) * NN + n];
        float x1 = x[(b * 3 + 1) * NN + n];
        float x2 = x[(b * 3 + 2) * NN + n];
        float* d = g_f0 + (size_t)t * 4;
        d[0] = x0; d[1] = x1; d[2] = x2; d[3] = 0.f;
        float a = fmaf(x0, x0, 0.f);
        a = fmaf(x1, x1, a);
        a = fmaf(x2, x2, a);
        g_xx[t] = a;
    } else if (bx == 32) {
        for (int t = threadIdx.x; t < O5; t += 256) { g_sum[t] = 0.f; g_sq[t] = 0.f; }
        if (threadIdx.x == 0) { g_cnt = 0; g_cnt2 = 0; g_flag = 0; }
    } else {
        int t = (bx - 33) * 256 + threadIdx.x;
        const float* W; int C, O, woff, local;
        if (t < 256)        { W = W1; C = 3;   O = 64;  woff = 0;     local = t; }          // CP=4
        else if (t < 4352)  { W = W2; C = 64;  O = 64;  woff = 256;   local = t - 256; }
        else if (t < 12544) { W = W3; C = 64;  O = 128; woff = 4352;  local = t - 4352; }
        else if (t < 45312) { W = W4; C = 128; O = 256; woff = 12544; local = t - 12544; }
        else return;
        int c = local / O, o = local % O;
        float wa = 0.f, wb = 0.f;
        if (c < C) {
            wa = W[o * (2 * C) + c];
            wb = W[o * (2 * C) + C + c];
        }
        int idx = woff + (c >> 1) * 2 * O + 2 * o + (c & 1);
        g_wa[idx] = wa;
        g_wu[idx] = wb - wa;
    }
}

// -------- neg pairwise distance Gram GEMM: symmetric, 128x128 tile, 8x8, f32x2 --------
__global__ __launch_bounds__(256, 2) void kd_kernel(int src, int off, int stride, int C) {
    __shared__ __align__(16) float Ad[16 * 260];
    __shared__ __align__(16) float Bs_[16 * 132];
    int b = blockIdx.z;
    int bi = 0, rem = blockIdx.x;
    while (rem >= 8 - bi) { rem -= 8 - bi; bi++; }
    int bj = bi + rem;
    int ib = bi * 128, jb = bj * 128;
    int tid = threadIdx.x;
    int tx = tid & 15, ty = tid >> 4;
    const float* fb = featPtr(src, off) + (size_t)b * NN * stride;

    ull acc[8][4];
#pragma unroll
    for (int i = 0; i < 8; i++)
#pragma unroll
        for (int j = 0; j < 4; j++) acc[i][j] = 0ull;

    int nch = (C + 15) >> 4;
    for (int cc = 0; cc < nch; cc++) {
#pragma unroll
        for (int h = 0; h < 2; h++) {
            int f4i = h * 256 + tid;
            int r = f4i >> 2;
            int cq = f4i & 3;
            int cg0 = (cc << 4) + cq * 4;
            float4 av, bv;
            if (cg0 < C) {
                av = *(const float4*)&fb[(size_t)(ib + r) * stride + cg0];
                bv = *(const float4*)&fb[(size_t)(jb + r) * stride + cg0];
            } else {
                av = make_float4(0.f, 0.f, 0.f, 0.f);
                bv = av;
            }
            int cb_ = cq * 4;
            *(ull*)&Ad[(cb_ + 0) * 260 + 2 * r] = bcast2(av.x);
            *(ull*)&Ad[(cb_ + 1) * 260 + 2 * r] = bcast2(av.y);
            *(ull*)&Ad[(cb_ + 2) * 260 + 2 * r] = bcast2(av.z);
            *(ull*)&Ad[(cb_ + 3) * 260 + 2 * r] = bcast2(av.w);
            Bs_[(cb_ + 0) * 132 + r] = bv.x;
            Bs_[(cb_ + 1) * 132 + r] = bv.y;
            Bs_[(cb_ + 2) * 132 + r] = bv.z;
            Bs_[(cb_ + 3) * 132 + r] = bv.w;
        }
        __syncthreads();
#pragma unroll
        for (int c = 0; c < 16; c++) {
            const float4* arow = (const float4*)&Ad[c * 260 + ty * 16];
            const float4* brow = (const float4*)&Bs_[c * 132 + tx * 8];
            float4 bq0 = brow[0];
            float4 bq1 = brow[1];
            ull b0 = *(ull*)&bq0.x, b1 = *(ull*)&bq0.z;
            ull b2 = *(ull*)&bq1.x, b3 = *(ull*)&bq1.z;
#pragma unroll
            for (int iq = 0; iq < 4; iq++) {
                float4 aq = arow[iq];
                ull a0 = *(ull*)&aq.x;
                ull a1 = *(ull*)&aq.z;
                int i0 = 2 * iq, i1 = 2 * iq + 1;
                acc[i0][0] = ffma2(a0, b0, acc[i0][0]);
                acc[i0][1] = ffma2(a0, b1, acc[i0][1]);
                acc[i0][2] = ffma2(a0, b2, acc[i0][2]);
                acc[i0][3] = ffma2(a0, b3, acc[i0][3]);
                acc[i1][0] = ffma2(a1, b0, acc[i1][0]);
                acc[i1][1] = ffma2(a1, b1, acc[i1][1]);
                acc[i1][2] = ffma2(a1, b2, acc[i1][2]);
                acc[i1][3] = ffma2(a1, b3, acc[i1][3]);
            }
        }
        __syncthreads();
    }

    const float* xxb = g_xx + b * NN;
    float xm[8], xn[8];
#pragma unroll
    for (int j = 0; j < 8; j++) xm[j] = xxb[jb + tx * 8 + j];
#pragma unroll
    for (int i = 0; i < 8; i++) xn[i] = xxb[ib + ty * 8 + i];
    float* nd = g_nd + (size_t)b * NN * NN;

#pragma unroll
    for (int i = 0; i < 8; i++) {
        float v[8];
#pragma unroll
        for (int j = 0; j < 4; j++) unpack2(acc[i][j], v[2 * j], v[2 * j + 1]);
        float4 o0, o1;
        o0.x = 2.f * v[0] - xn[i] - xm[0];
        o0.y = 2.f * v[1] - xn[i] - xm[1];
        o0.z = 2.f * v[2] - xn[i] - xm[2];
        o0.w = 2.f * v[3] - xn[i] - xm[3];
        o1.x = 2.f * v[4] - xn[i] - xm[4];
        o1.y = 2.f * v[5] - xn[i] - xm[5];
        o1.z = 2.f * v[6] - xn[i] - xm[6];
        o1.w = 2.f * v[7] - xn[i] - xm[7];
        float4* dst = (float4*)(nd + (size_t)(ib + ty * 8 + i) * NN + jb + tx * 8);
        dst[0] = o0;
        dst[1] = o1;
    }
    if (bi != bj) {
#pragma unroll
        for (int j = 0; j < 8; j++) {
            float tmp[8];
#pragma unroll
            for (int i = 0; i < 8; i++) {
                float lo, hi;
                unpack2(acc[i][j >> 1], lo, hi);
                float mv = (j & 1) ? hi : lo;
                tmp[i] = 2.f * mv - xn[i] - xm[j];
            }
            float4* d2 = (float4*)(nd + (size_t)(jb + tx * 8 + j) * NN + ib + ty * 8);
            d2[0] = make_float4(tmp[0], tmp[1], tmp[2], tmp[3]);
            d2[1] = make_float4(tmp[4], tmp[5], tmp[6], tmp[7]);
        }
    }
}

__device__ __forceinline__ ull packkey(float v, int gidx) {
    unsigned bb = __float_as_uint(v);
    bb ^= (unsigned)(((int)bb >> 31)) | 0x80000000u;
    return ((ull)bb << 32) | (ull)(1023 - gidx);
}

// -------- fused: top-20 (blocks 0..1023) + v/u GEMM f32x2 (rest) --------
__global__ __launch_bounds__(256, 4) void tk2_kernel(int src, int off, int stride,
                                                     int C, int CP, int O, int och, int woff) {
    __shared__ __align__(8) float sf[16 * 128];
    if (blockIdx.x < 1024) {
        int wid = threadIdx.x >> 5;
        int lane = threadIdx.x & 31;
        int rowg = blockIdx.x * 8 + wid;
        const float* row = g_nd + (size_t)rowg * NN;

        float vals[32];
#pragma unroll
        for (int j = 0; j < 32; j++) vals[j] = row[j * 32 + lane];

        unsigned alive = 0xffffffffu;
        float qv0, qv1, qv2, qv3;
        int qj0, qj1, qj2, qj3;

#define RESCANQ(Q, QV, QJ)                                            \
        {                                                             \
            QV = -3.0e38f; QJ = (Q) * 8;                              \
            _Pragma("unroll")                                         \
            for (int j0 = 0; j0 < 8; j0++) {                          \
                int j = (Q) * 8 + j0;                                 \
                float v = ((alive >> j) & 1u) ? vals[j] : -3.0e38f;   \
                if (v > QV) { QV = v; QJ = j; }                       \
            }                                                         \
        }

        RESCANQ(0, qv0, qj0)
        RESCANQ(1, qv1, qj1)
        RESCANQ(2, qv2, qj2)
        RESCANQ(3, qv3, qj3)

        float lv = qv0; int li = qj0;
        if (qv1 > lv) { lv = qv1; li = qj1; }
        if (qv2 > lv) { lv = qv2; li = qj2; }
        if (qv3 > lv) { lv = qv3; li = qj3; }

        int myout = 0;
        for (int k = 0; k < KK; k++) {
            ull key = packkey(lv, li * 32 + lane);
#pragma unroll
            for (int s = 16; s; s >>= 1) {
                ull ok = __shfl_xor_sync(0xffffffffu, key, s);
                key = (ok > key) ? ok : key;
            }
            int gidx = 1023 - (int)(key & 0xffffffffu);
            if (lane == k) myout = gidx;
            if (lane == (gidx & 31)) {
                int jrem = gidx >> 5;
                alive &= ~(1u << jrem);
                int q = jrem >> 3;
                if (q == 0)      RESCANQ(0, qv0, qj0)
                else if (q == 1) RESCANQ(1, qv1, qj1)
                else if (q == 2) RESCANQ(2, qv2, qj2)
                else             RESCANQ(3, qv3, qj3)
                lv = qv0; li = qj0;
                if (qv1 > lv) { lv = qv1; li = qj1; }
                if (qv2 > lv) { lv = qv2; li = qj2; }
                if (qv3 > lv) { lv = qv3; li = qj3; }
            }
        }
        if (lane < KK) g_idx[rowg * KK + lane] = myout;
#undef RESCANQ
    } else {
        int kb = blockIdx.x - 1024;
        int bpb = 64 * och;
        int b = kb / bpb;
        int rm = kb % bpb;
        int n0 = (rm / och) * 16;
        int o0 = (rm % och) * 64;
        int og = threadIdx.x & 63;
        int pg = threadIdx.x >> 6;
        int o = o0 + og;
        const float* fb = featPtr(src, off) + ((size_t)b * NN + n0) * stride;
        for (int l = threadIdx.x; l < 16 * CP; l += 256) {
            int p = l / CP, c = l % CP;
            sf[p * CP + c] = (c < C) ? fb[(size_t)p * stride + c] : 0.f;
        }
        __syncthreads();
        ull va2[4], vu2[4];
#pragma unroll
        for (int p = 0; p < 4; p++) { va2[p] = 0ull; vu2[p] = 0ull; }
        const ull* wap = (const ull*)(g_wa + woff + 2 * o);
        const ull* wup = (const ull*)(g_wu + woff + 2 * o);
        int nhp = CP >> 1;
        const ull* sfp = (const ull*)sf + pg * 4 * nhp;
        for (int cp = 0; cp < nhp; cp++) {
            ull w2a = wap[cp * O];
            ull w2u = wup[cp * O];
#pragma unroll
            for (int p = 0; p < 4; p++) {
                ull f2 = sfp[p * nhp + cp];
                va2[p] = ffma2(w2a, f2, va2[p]);
                vu2[p] = ffma2(w2u, f2, vu2[p]);
            }
        }
#pragma unroll
        for (int p = 0; p < 4; p++) {
            float lo, hi;
            unpack2(va2[p], lo, hi);
            float va = lo + hi;
            unpack2(vu2[p], lo, hi);
            float vu = lo + hi;
            size_t idx = ((size_t)b * NN + n0 + pg * 4 + p) * O + o;
            g_v[idx] = va;
            g_u[idx] = vu;
        }
    }
}

// -------- gather + k-reduce + stats + GRID-SYNC + BN apply + next-layer xx --------
// 512 blocks <= co-residency capacity (4 blocks/SM * 148 = 592): counter-based
// grid barrier is deadlock-free. max/min stay smem-resident; no k4b pass.
__global__ __launch_bounds__(256, 4) void k3_kernel(const float* __restrict__ gam,
                          const float* __restrict__ bet, int O, int coff, int do_xx) {
    __shared__ float smx[256 * 16];
    __shared__ float smn[256 * 16];
    __shared__ float sxx[16 * 8];
    __shared__ int isLast;
    int b = blockIdx.y;
    int n0 = blockIdx.x * 16;
    int tid = threadIdx.x;
    int o = tid % O;
    int pp = tid / O;
    int ppl = 256 / O;
    int ppp = 16 / ppl;
    size_t base = (size_t)b * NN;
    float s = 0.f, q = 0.f;
    for (int p = 0; p < ppp; p++) {
        int n = n0 + pp * ppp + p;
        const int* id = g_idx + (base + n) * KK;
        float uu = g_u[(base + n) * O + o];
        float mx = -3.0e38f, mn = 3.0e38f;
#pragma unroll
        for (int k = 0; k < KK; k++) {
            int j = id[k];
            float y = g_v[(base + j) * O + o] + uu;
            mx = fmaxf(mx, y);
            mn = fminf(mn, y);
            s += y;
            q = fmaf(y, y, q);
        }
        smx[tid * 16 + p] = mx;
        smn[tid * 16 + p] = mn;
    }
    atomicAdd(&g_sum[o], s);
    atomicAdd(&g_sq[o], q);

    // grid barrier phase 1: arrival (all block writes released first)
    __syncthreads();
    __threadfence();
    if (tid == 0) isLast = (atomicAdd(&g_cnt, 1) == 511);
    __syncthreads();
    if (isLast) {
        if (tid < O) {
            volatile float* vs = g_sum;
            volatile float* vq = g_sq;
            float cnt = (float)(BB * NN * KK);
            float m = vs[o] / cnt;
            float var = vq[o] / cnt - m * m;
            float sc = gam[o] * rsqrtf(var + 1e-5f);
            g_scale[o] = sc;
            g_bias[o] = bet[o] - m * sc;
        }
        __syncthreads();
        // reset stats for the next consumer (next k3 / f1)
        for (int z = tid; z < O5; z += 256) { g_sum[z] = 0.f; g_sq[z] = 0.f; }
        __threadfence();
        __syncthreads();
        if (tid == 0) g_flag = 1;   // release
    }
    // phase 2: all blocks wait for scale/bias
    if (tid == 0) {
        volatile int* vf = &g_flag;
        while (*vf == 0) {}
    }
    __syncthreads();
    __threadfence();                // acquire

    // apply BN + lrelu from smem-resident max/min; write cat; fused xx
    volatile float* vsc = g_scale;
    volatile float* vbi = g_bias;
    float sc = vsc[o];
    float bi = vbi[o];
    int wip = o >> 5;               // warp index within a point's O channels
    int wpp = O >> 5;               // warps per point
    int lane = tid & 31;
    for (int p = 0; p < ppp; p++) {
        int n = n0 + pp * ppp + p;
        float mx = smx[tid * 16 + p];
        float mn = smn[tid * 16 + p];
        float sel = (sc >= 0.f) ? mx : mn;
        float y = fmaf(sc, sel, bi);
        float act = (y >= 0.f) ? y : 0.2f * y;
        g_cat[(base + n) * CAT + coff + o] = act;
        if (do_xx) {
            float a2 = act * act;
#pragma unroll
            for (int st = 16; st; st >>= 1) a2 += __shfl_xor_sync(0xffffffffu, a2, st);
            if (lane == 0) sxx[(pp * ppp + p) * 8 + wip] = a2;
        }
    }
    if (do_xx) {
        __syncthreads();
        if (tid < 16) {
            float a = 0.f;
            for (int w = 0; w < wpp; w++) a += sxx[tid * 8 + w];
            g_xx[base + n0 + tid] = a;
        }
    }

    // phase 3: completion — last finisher resets sync vars (graph-replay safe)
    __syncthreads();
    __threadfence();
    if (tid == 0) {
        if (atomicAdd(&g_cnt2, 1) == 511) {
            g_cnt = 0;
            g_cnt2 = 0;
            g_flag = 0;
        }
    }
}

// -------- final conv1d GEMM + fused n-stats + last-block final BN/lrelu/max --------
__global__ __launch_bounds__(256, 2) void f1_kernel(const float* __restrict__ W5,
                                                    const float* __restrict__ g5,
                                                    const float* __restrict__ b5,
                                                    float* __restrict__ out) {
    __shared__ __align__(16) float Ad[16 * 260];
    __shared__ __align__(16) float Bs_[16 * 132];
    int ob = blockIdx.x * 128;
    int nb = blockIdx.y * 128;
    int b = blockIdx.z;
    int tid = threadIdx.x;
    int tx = tid & 15, ty = tid >> 4;
    const float* cb = g_cat + (size_t)b * NN * CAT;

    ull acc[8][4];
#pragma unroll
    for (int i = 0; i < 8; i++)
#pragma unroll
        for (int j = 0; j < 4; j++) acc[i][j] = 0ull;

    for (int cc = 0; cc < 32; cc++) {
#pragma unroll
        for (int h = 0; h < 2; h++) {
            int f4i = h * 256 + tid;
            int r = f4i >> 2;
            int cq = f4i & 3;
            int cg0 = (cc << 4) + cq * 4;
            float4 av = *(const float4*)&W5[(size_t)(ob + r) * 512 + cg0];
            float4 bv = *(const float4*)&cb[(size_t)(nb + r) * 512 + cg0];
            int cb_ = cq * 4;
            *(ull*)&Ad[(cb_ + 0) * 260 + 2 * r] = bcast2(av.x);
            *(ull*)&Ad[(cb_ + 1) * 260 + 2 * r] = bcast2(av.y);
            *(ull*)&Ad[(cb_ + 2) * 260 + 2 * r] = bcast2(av.z);
            *(ull*)&Ad[(cb_ + 3) * 260 + 2 * r] = bcast2(av.w);
            Bs_[(cb_ + 0) * 132 + r] = bv.x;
            Bs_[(cb_ + 1) * 132 + r] = bv.y;
            Bs_[(cb_ + 2) * 132 + r] = bv.z;
            Bs_[(cb_ + 3) * 132 + r] = bv.w;
        }
        __syncthreads();
#pragma unroll
        for (int c = 0; c < 16; c++) {
            const float4* arow = (const float4*)&Ad[c * 260 + ty * 16];
            const float4* brow = (const float4*)&Bs_[c * 132 + tx * 8];
            float4 bq0 = brow[0];
            float4 bq1 = brow[1];
            ull b0 = *(ull*)&bq0.x, b1 = *(ull*)&bq0.z;
            ull b2 = *(ull*)&bq1.x, b3 = *(ull*)&bq1.z;
#pragma unroll
            for (int iq = 0; iq < 4; iq++) {
                float4 aq = arow[iq];
                ull a0 = *(ull*)&aq.x;
                ull a1 = *(ull*)&aq.z;
                int i0 = 2 * iq, i1 = 2 * iq + 1;
                acc[i0][0] = ffma2(a0, b0, acc[i0][0]);
                acc[i0][1] = ffma2(a0, b1, acc[i0][1]);
                acc[i0][2] = ffma2(a0, b2, acc[i0][2]);
                acc[i0][3] = ffma2(a0, b3, acc[i0][3]);
                acc[i1][0] = ffma2(a1, b0, acc[i1][0]);
                acc[i1][1] = ffma2(a1, b1, acc[i1][1]);
                acc[i1][2] = ffma2(a1, b2, acc[i1][2]);
                acc[i1][3] = ffma2(a1, b3, acc[i1][3]);
            }
        }
        __syncthreads();
    }

#pragma unroll
    for (int i = 0; i < 8; i++) {
        float v[8];
#pragma unroll
        for (int j = 0; j < 4; j++) unpack2(acc[i][j], v[2 * j], v[2 * j + 1]);
        float mx = v[0], mn = v[0], s = v[0], q = v[0] * v[0];
#pragma unroll
        for (int j = 1; j < 8; j++) {
            mx = fmaxf(mx, v[j]);
            mn = fminf(mn, v[j]);
            s += v[j];
            q = fmaf(v[j], v[j], q);
        }
#pragma unroll
        for (int st = 8; st; st >>= 1) {
            mx = fmaxf(mx, __shfl_xor_sync(0xffffffffu, mx, st));
            mn = fminf(mn, __shfl_xor_sync(0xffffffffu, mn, st));
            s += __shfl_xor_sync(0xffffffffu, s, st);
            q += __shfl_xor_sync(0xffffffffu, q, st);
        }
        if (tx == 0) {
            int o = ob + ty * 8 + i;
            g_pmax[((size_t)b * O5 + o) * 8 + blockIdx.y] = mx;
            g_pmin[((size_t)b * O5 + o) * 8 + blockIdx.y] = mn;
            atomicAdd(&g_sum[o], s);
            atomicAdd(&g_sq[o], q);
        }
    }

    __syncthreads();
    __threadfence();
    __shared__ int isLast;
    if (tid == 0) isLast = (atomicAdd(&g_cnt, 1) == 511);
    __syncthreads();
    if (isLast) {
        volatile float* vs = g_sum;
        volatile float* vq = g_sq;
        for (int t = tid; t < BB * O5; t += 256) {
            int bb2 = t / O5, o = t % O5;
            float m = vs[o] / 8192.f;
            float var = vq[o] / 8192.f - m * m;
            float sc = g5[o] * rsqrtf(var + 1e-5f);
            float bi = b5[o] - m * sc;
            volatile float* pm = (sc >= 0.f) ? g_pmax : g_pmin;
            size_t base = ((size_t)bb2 * O5 + o) * 8;
            float sel = pm[base];
            if (sc >= 0.f) {
                for (int i = 1; i < 8; i++) sel = fmaxf(sel, pm[base + i]);
            } else {
                for (int i = 1; i < 8; i++) sel = fminf(sel, pm[base + i]);
            }
            float y = fmaf(sc, sel, bi);
            out[t] = (y >= 0.f) ? y : 0.2f * y;
        }
        if (tid == 0) g_cnt = 0;
    }
}

extern "C" void kernel_launch(void* const* d_in, const int* in_sizes, int n_in,
                              void* d_out, int out_size) {
    const float* x  = (const float*)d_in[0];
    const float* Wl[4] = {(const float*)d_in[1], (const float*)d_in[4],
                          (const float*)d_in[7], (const float*)d_in[10]};
    const float* gl[4] = {(const float*)d_in[2], (const float*)d_in[5],
                          (const float*)d_in[8], (const float*)d_in[11]};
    const float* bl[4] = {(const float*)d_in[3], (const float*)d_in[6],
                          (const float*)d_in[9], (const float*)d_in[12]};
    const float* W5 = (const float*)d_in[13];
    const float* g5 = (const float*)d_in[14];
    const float* b5 = (const float*)d_in[15];
    float* out = (float*)d_out;

    prep0<<<210, 256>>>(x, Wl[0], Wl[1], Wl[2], Wl[3]);

    const int srcA[4]  = {0, 1, 1, 1};
    const int offA[4]  = {0, 0, 64, 128};
    const int CA[4]    = {3, 64, 64, 128};
    const int CPA[4]   = {4, 64, 64, 128};
    const int OA[4]    = {64, 64, 128, 256};
    const int coffA[4] = {0, 64, 128, 256};
    const int woffA[4] = {0, 256, 4352, 12544};

    for (int L = 0; L < 4; L++) {
        int src = srcA[L], off = offA[L], C = CA[L], CP = CPA[L], O = OA[L];
        int coff = coffA[L], woff = woffA[L];
        int stride = src ? CAT : 4;
        int och = O / 64;
        kd_kernel<<<dim3(36, 1, BB), 256>>>(src, off, stride, C);
        tk2_kernel<<<1024 + 512 * och, 256>>>(src, off, stride, C, CP, O, och, woff);
        k3_kernel<<<dim3(64, BB), 256>>>(gl[L], bl[L], O, coff, (L < 3) ? 1 : 0);
    }

    f1_kernel<<<dim3(8, 8, BB), 256>>>(W5, g5, b5, out);
}

// round 15
// speedup vs baseline: 1.8248x; 1.0252x over previous
#include <cuda_runtime.h>

#define BB 8
#define NN 1024
#define KK 20
#define CAT 512
#define O5 1024

typedef unsigned long long ull;

__device__ __forceinline__ ull ffma2(ull a, ull b, ull c) {
    ull d;
    asm("fma.rn.f32x2 %0, %1, %2, %3;" : "=l"(d) : "l"(a), "l"(b), "l"(c));
    return d;
}
__device__ __forceinline__ ull bcast2(float v) {
    ull d;
    asm("mov.b64 %0, {%1, %1};" : "=l"(d) : "f"(v));
    return d;
}
__device__ __forceinline__ void unpack2(ull p, float& lo, float& hi) {
    asm("mov.b64 {%0, %1}, %2;" : "=f"(lo), "=f"(hi) : "l"(p));
}
__device__ __forceinline__ unsigned mono32(float v) {
    unsigned bb = __float_as_uint(v);
    return bb ^ ((unsigned)(((int)bb >> 31)) | 0x80000000u);
}

// -------- static device workspaces --------
__device__ __align__(16) float g_f0[BB * NN * 4];
__device__ __align__(16) float g_cat[BB * NN * CAT];
__device__ float g_xx[BB * NN];
__device__ float g_nd[BB * NN * NN];
__device__ int   g_idx[BB * NN * KK];
__device__ float g_v[BB * NN * 256];
__device__ float g_u[BB * NN * 256];
__device__ __align__(8) float g_wa[64 * 1024];   // packed: pair-major {w[c],w[c+1]}
__device__ __align__(8) float g_wu[64 * 1024];
__device__ float g_sum[O5];
__device__ float g_sq[O5];
__device__ float g_pmax[BB * O5 * 8];
__device__ float g_pmin[BB * O5 * 8];
__device__ float g_scale[256];
__device__ float g_bias[256];
__device__ int   g_cnt;
__device__ int   g_cnt2;
__device__ int   g_flag;

__device__ __forceinline__ const float* featPtr(int src, int off) {
    return src ? (g_cat + off) : g_f0;
}

// -------- fused prep: transpose x + xx(layer1) + ALL W splits (pair-packed) + zero stats --------
__global__ void prep0(const float* __restrict__ x,
                      const float* __restrict__ W1, const float* __restrict__ W2,
                      const float* __restrict__ W3, const float* __restrict__ W4) {
    int bx = blockIdx.x;
    if (bx < 32) {
        int t = bx * 256 + threadIdx.x;
        int b = t / NN, n = t % NN;
        float x0 = x[(b * 3 + 0) * NN + n];
        float x1 = x[(b * 3 + 1) * NN + n];
        float x2 = x[(b * 3 + 2) * NN + n];
        float* d = g_f0 + (size_t)t * 4;
        d[0] = x0; d[1] = x1; d[2] = x2; d[3] = 0.f;
        float a = fmaf(x0, x0, 0.f);
        a = fmaf(x1, x1, a);
        a = fmaf(x2, x2, a);
        g_xx[t] = a;
    } else if (bx == 32) {
        for (int t = threadIdx.x; t < O5; t += 256) { g_sum[t] = 0.f; g_sq[t] = 0.f; }
        if (threadIdx.x == 0) { g_cnt = 0; g_cnt2 = 0; g_flag = 0; }
    } else {
        int t = (bx - 33) * 256 + threadIdx.x;
        const float* W; int C, O, woff, local;
        if (t < 256)        { W = W1; C = 3;   O = 64;  woff = 0;     local = t; }          // CP=4
        else if (t < 4352)  { W = W2; C = 64;  O = 64;  woff = 256;   local = t - 256; }
        else if (t < 12544) { W = W3; C = 64;  O = 128; woff = 4352;  local = t - 4352; }
        else if (t < 45312) { W = W4; C = 128; O = 256; woff = 12544; local = t - 12544; }
        else return;
        int c = local / O, o = local % O;
        float wa = 0.f, wb = 0.f;
        if (c < C) {
            wa = W[o * (2 * C) + c];
            wb = W[o * (2 * C) + C + c];
        }
        int idx = woff + (c >> 1) * 2 * O + 2 * o + (c & 1);
        g_wa[idx] = wa;
        g_wu[idx] = wb - wa;
    }
}

// -------- neg pairwise distance Gram GEMM: symmetric, 128x128 tile, 8x8, f32x2 --------
__global__ __launch_bounds__(256, 2) void kd_kernel(int src, int off, int stride, int C) {
    __shared__ __align__(16) float Ad[16 * 260];
    __shared__ __align__(16) float Bs_[16 * 132];
    int b = blockIdx.z;
    int bi = 0, rem = blockIdx.x;
    while (rem >= 8 - bi) { rem -= 8 - bi; bi++; }
    int bj = bi + rem;
    int ib = bi * 128, jb = bj * 128;
    int tid = threadIdx.x;
    int tx = tid & 15, ty = tid >> 4;
    const float* fb = featPtr(src, off) + (size_t)b * NN * stride;

    ull acc[8][4];
#pragma unroll
    for (int i = 0; i < 8; i++)
#pragma unroll
        for (int j = 0; j < 4; j++) acc[i][j] = 0ull;

    int nch = (C + 15) >> 4;
    for (int cc = 0; cc < nch; cc++) {
#pragma unroll
        for (int h = 0; h < 2; h++) {
            int f4i = h * 256 + tid;
            int r = f4i >> 2;
            int cq = f4i & 3;
            int cg0 = (cc << 4) + cq * 4;
            float4 av, bv;
            if (cg0 < C) {
                av = *(const float4*)&fb[(size_t)(ib + r) * stride + cg0];
                bv = *(const float4*)&fb[(size_t)(jb + r) * stride + cg0];
            } else {
                av = make_float4(0.f, 0.f, 0.f, 0.f);
                bv = av;
            }
            int cb_ = cq * 4;
            *(ull*)&Ad[(cb_ + 0) * 260 + 2 * r] = bcast2(av.x);
            *(ull*)&Ad[(cb_ + 1) * 260 + 2 * r] = bcast2(av.y);
            *(ull*)&Ad[(cb_ + 2) * 260 + 2 * r] = bcast2(av.z);
            *(ull*)&Ad[(cb_ + 3) * 260 + 2 * r] = bcast2(av.w);
            Bs_[(cb_ + 0) * 132 + r] = bv.x;
            Bs_[(cb_ + 1) * 132 + r] = bv.y;
            Bs_[(cb_ + 2) * 132 + r] = bv.z;
            Bs_[(cb_ + 3) * 132 + r] = bv.w;
        }
        __syncthreads();
#pragma unroll
        for (int c = 0; c < 16; c++) {
            const float4* arow = (const float4*)&Ad[c * 260 + ty * 16];
            const float4* brow = (const float4*)&Bs_[c * 132 + tx * 8];
            float4 bq0 = brow[0];
            float4 bq1 = brow[1];
            ull b0 = *(ull*)&bq0.x, b1 = *(ull*)&bq0.z;
            ull b2 = *(ull*)&bq1.x, b3 = *(ull*)&bq1.z;
#pragma unroll
            for (int iq = 0; iq < 4; iq++) {
                float4 aq = arow[iq];
                ull a0 = *(ull*)&aq.x;
                ull a1 = *(ull*)&aq.z;
                int i0 = 2 * iq, i1 = 2 * iq + 1;
                acc[i0][0] = ffma2(a0, b0, acc[i0][0]);
                acc[i0][1] = ffma2(a0, b1, acc[i0][1]);
                acc[i0][2] = ffma2(a0, b2, acc[i0][2]);
                acc[i0][3] = ffma2(a0, b3, acc[i0][3]);
                acc[i1][0] = ffma2(a1, b0, acc[i1][0]);
                acc[i1][1] = ffma2(a1, b1, acc[i1][1]);
                acc[i1][2] = ffma2(a1, b2, acc[i1][2]);
                acc[i1][3] = ffma2(a1, b3, acc[i1][3]);
            }
        }
        __syncthreads();
    }

    const float* xxb = g_xx + b * NN;
    float xm[8], xn[8];
#pragma unroll
    for (int j = 0; j < 8; j++) xm[j] = xxb[jb + tx * 8 + j];
#pragma unroll
    for (int i = 0; i < 8; i++) xn[i] = xxb[ib + ty * 8 + i];
    float* nd = g_nd + (size_t)b * NN * NN;

#pragma unroll
    for (int i = 0; i < 8; i++) {
        float v[8];
#pragma unroll
        for (int j = 0; j < 4; j++) unpack2(acc[i][j], v[2 * j], v[2 * j + 1]);
        float4 o0, o1;
        o0.x = 2.f * v[0] - xn[i] - xm[0];
        o0.y = 2.f * v[1] - xn[i] - xm[1];
        o0.z = 2.f * v[2] - xn[i] - xm[2];
        o0.w = 2.f * v[3] - xn[i] - xm[3];
        o1.x = 2.f * v[4] - xn[i] - xm[4];
        o1.y = 2.f * v[5] - xn[i] - xm[5];
        o1.z = 2.f * v[6] - xn[i] - xm[6];
        o1.w = 2.f * v[7] - xn[i] - xm[7];
        float4* dst = (float4*)(nd + (size_t)(ib + ty * 8 + i) * NN + jb + tx * 8);
        dst[0] = o0;
        dst[1] = o1;
    }
    if (bi != bj) {
#pragma unroll
        for (int j = 0; j < 8; j++) {
            float tmp[8];
#pragma unroll
            for (int i = 0; i < 8; i++) {
                float lo, hi;
                unpack2(acc[i][j >> 1], lo, hi);
                float mv = (j & 1) ? hi : lo;
                tmp[i] = 2.f * mv - xn[i] - xm[j];
            }
            float4* d2 = (float4*)(nd + (size_t)(jb + tx * 8 + j) * NN + ib + ty * 8);
            d2[0] = make_float4(tmp[0], tmp[1], tmp[2], tmp[3]);
            d2[1] = make_float4(tmp[4], tmp[5], tmp[6], tmp[7]);
        }
    }
}

// -------- fused: top-20 (blocks 0..1023, REDUX selection) + v/u GEMM f32x2 (rest) --------
__global__ __launch_bounds__(256, 4) void tk2_kernel(int src, int off, int stride,
                                                     int C, int CP, int O, int och, int woff) {
    __shared__ __align__(8) float sf[16 * 128];
    if (blockIdx.x < 1024) {
        int wid = threadIdx.x >> 5;
        int lane = threadIdx.x & 31;
        int rowg = blockIdx.x * 8 + wid;
        const float* row = g_nd + (size_t)rowg * NN;

        float vals[32];
#pragma unroll
        for (int j = 0; j < 32; j++) vals[j] = row[j * 32 + lane];

        unsigned alive = 0xffffffffu;
        float qv0, qv1, qv2, qv3;
        int qj0, qj1, qj2, qj3;

#define RESCANQ(Q, QV, QJ)                                            \
        {                                                             \
            QV = -3.0e38f; QJ = (Q) * 8;                              \
            _Pragma("unroll")                                         \
            for (int j0 = 0; j0 < 8; j0++) {                          \
                int j = (Q) * 8 + j0;                                 \
                float v = ((alive >> j) & 1u) ? vals[j] : -3.0e38f;   \
                if (v > QV) { QV = v; QJ = j; }                       \
            }                                                         \
        }

        RESCANQ(0, qv0, qj0)
        RESCANQ(1, qv1, qj1)
        RESCANQ(2, qv2, qj2)
        RESCANQ(3, qv3, qj3)

        float lv = qv0; int li = qj0;
        if (qv1 > lv) { lv = qv1; li = qj1; }
        if (qv2 > lv) { lv = qv2; li = qj2; }
        if (qv3 > lv) { lv = qv3; li = qj3; }
        unsigned mkey = mono32(lv);

        int myout = 0;
        for (int k = 0; k < KK; k++) {
            unsigned bm = __reduce_max_sync(0xffffffffu, mkey);
            unsigned cand = (mkey == bm) ? (unsigned)(li * 32 + lane) : 0xffffffffu;
            unsigned gidx = __reduce_min_sync(0xffffffffu, cand);
            if (lane == k) myout = (int)gidx;
            if (lane == (gidx & 31)) {
                int jrem = (int)(gidx >> 5);
                alive &= ~(1u << jrem);
                int q = jrem >> 3;
                if (q == 0)      RESCANQ(0, qv0, qj0)
                else if (q == 1) RESCANQ(1, qv1, qj1)
                else if (q == 2) RESCANQ(2, qv2, qj2)
                else             RESCANQ(3, qv3, qj3)
                lv = qv0; li = qj0;
                if (qv1 > lv) { lv = qv1; li = qj1; }
                if (qv2 > lv) { lv = qv2; li = qj2; }
                if (qv3 > lv) { lv = qv3; li = qj3; }
                mkey = mono32(lv);
            }
        }
        if (lane < KK) g_idx[rowg * KK + lane] = myout;
#undef RESCANQ
    } else {
        int kb = blockIdx.x - 1024;
        int bpb = 64 * och;
        int b = kb / bpb;
        int rm = kb % bpb;
        int n0 = (rm / och) * 16;
        int o0 = (rm % och) * 64;
        int og = threadIdx.x & 63;
        int pg = threadIdx.x >> 6;
        int o = o0 + og;
        const float* fb = featPtr(src, off) + ((size_t)b * NN + n0) * stride;
        for (int l = threadIdx.x; l < 16 * CP; l += 256) {
            int p = l / CP, c = l % CP;
            sf[p * CP + c] = (c < C) ? fb[(size_t)p * stride + c] : 0.f;
        }
        __syncthreads();
        ull va2[4], vu2[4];
#pragma unroll
        for (int p = 0; p < 4; p++) { va2[p] = 0ull; vu2[p] = 0ull; }
        const ull* wap = (const ull*)(g_wa + woff + 2 * o);
        const ull* wup = (const ull*)(g_wu + woff + 2 * o);
        int nhp = CP >> 1;
        const ull* sfp = (const ull*)sf + pg * 4 * nhp;
        for (int cp = 0; cp < nhp; cp++) {
            ull w2a = wap[cp * O];
            ull w2u = wup[cp * O];
#pragma unroll
            for (int p = 0; p < 4; p++) {
                ull f2 = sfp[p * nhp + cp];
                va2[p] = ffma2(w2a, f2, va2[p]);
                vu2[p] = ffma2(w2u, f2, vu2[p]);
            }
        }
#pragma unroll
        for (int p = 0; p < 4; p++) {
            float lo, hi;
            unpack2(va2[p], lo, hi);
            float va = lo + hi;
            unpack2(vu2[p], lo, hi);
            float vu = lo + hi;
            size_t idx = ((size_t)b * NN + n0 + pg * 4 + p) * O + o;
            g_v[idx] = va;
            g_u[idx] = vu;
        }
    }
}

// -------- gather + k-reduce + stats + GRID-SYNC + BN apply + next-layer xx --------
__global__ __launch_bounds__(256, 4) void k3_kernel(const float* __restrict__ gam,
                          const float* __restrict__ bet, int O, int coff, int do_xx) {
    __shared__ float smx[256 * 16];
    __shared__ float smn[256 * 16];
    __shared__ float sxx[16 * 8];
    __shared__ int isLast;
    int b = blockIdx.y;
    int n0 = blockIdx.x * 16;
    int tid = threadIdx.x;
    int o = tid % O;
    int pp = tid / O;
    int ppl = 256 / O;
    int ppp = 16 / ppl;
    size_t base = (size_t)b * NN;
    float s = 0.f, q = 0.f;
    for (int p = 0; p < ppp; p++) {
        int n = n0 + pp * ppp + p;
        const int* id = g_idx + (base + n) * KK;
        float uu = g_u[(base + n) * O + o];
        float mx = -3.0e38f, mn = 3.0e38f;
#pragma unroll
        for (int k = 0; k < KK; k++) {
            int j = id[k];
            float y = g_v[(base + j) * O + o] + uu;
            mx = fmaxf(mx, y);
            mn = fminf(mn, y);
            s += y;
            q = fmaf(y, y, q);
        }
        smx[tid * 16 + p] = mx;
        smn[tid * 16 + p] = mn;
    }
    atomicAdd(&g_sum[o], s);
    atomicAdd(&g_sq[o], q);

    __syncthreads();
    __threadfence();
    if (tid == 0) isLast = (atomicAdd(&g_cnt, 1) == 511);
    __syncthreads();
    if (isLast) {
        if (tid < O) {
            volatile float* vs = g_sum;
            volatile float* vq = g_sq;
            float cnt = (float)(BB * NN * KK);
            float m = vs[o] / cnt;
            float var = vq[o] / cnt - m * m;
            float sc = gam[o] * rsqrtf(var + 1e-5f);
            g_scale[o] = sc;
            g_bias[o] = bet[o] - m * sc;
        }
        __syncthreads();
        for (int z = tid; z < O5; z += 256) { g_sum[z] = 0.f; g_sq[z] = 0.f; }
        __threadfence();
        __syncthreads();
        if (tid == 0) g_flag = 1;
    }
    if (tid == 0) {
        volatile int* vf = &g_flag;
        while (*vf == 0) {}
    }
    __syncthreads();
    __threadfence();

    volatile float* vsc = g_scale;
    volatile float* vbi = g_bias;
    float sc = vsc[o];
    float bi = vbi[o];
    int wip = o >> 5;
    int wpp = O >> 5;
    int lane = tid & 31;
    for (int p = 0; p < ppp; p++) {
        int n = n0 + pp * ppp + p;
        float mx = smx[tid * 16 + p];
        float mn = smn[tid * 16 + p];
        float sel = (sc >= 0.f) ? mx : mn;
        float y = fmaf(sc, sel, bi);
        float act = (y >= 0.f) ? y : 0.2f * y;
        g_cat[(base + n) * CAT + coff + o] = act;
        if (do_xx) {
            float a2 = act * act;
#pragma unroll
            for (int st = 16; st; st >>= 1) a2 += __shfl_xor_sync(0xffffffffu, a2, st);
            if (lane == 0) sxx[(pp * ppp + p) * 8 + wip] = a2;
        }
    }
    if (do_xx) {
        __syncthreads();
        if (tid < 16) {
            float a = 0.f;
            for (int w = 0; w < wpp; w++) a += sxx[tid * 8 + w];
            g_xx[base + n0 + tid] = a;
        }
    }

    __syncthreads();
    __threadfence();
    if (tid == 0) {
        if (atomicAdd(&g_cnt2, 1) == 511) {
            g_cnt = 0;
            g_cnt2 = 0;
            g_flag = 0;
        }
    }
}

// -------- final conv1d GEMM + fused n-stats + last-block final BN/lrelu/max --------
__global__ __launch_bounds__(256, 2) void f1_kernel(const float* __restrict__ W5,
                                                    const float* __restrict__ g5,
                                                    const float* __restrict__ b5,
                                                    float* __restrict__ out) {
    __shared__ __align__(16) float Ad[16 * 260];
    __shared__ __align__(16) float Bs_[16 * 132];
    int ob = blockIdx.x * 128;
    int nb = blockIdx.y * 128;
    int b = blockIdx.z;
    int tid = threadIdx.x;
    int tx = tid & 15, ty = tid >> 4;
    const float* cb = g_cat + (size_t)b * NN * CAT;

    ull acc[8][4];
#pragma unroll
    for (int i = 0; i < 8; i++)
#pragma unroll
        for (int j = 0; j < 4; j++) acc[i][j] = 0ull;

    for (int cc = 0; cc < 32; cc++) {
#pragma unroll
        for (int h = 0; h < 2; h++) {
            int f4i = h * 256 + tid;
            int r = f4i >> 2;
            int cq = f4i & 3;
            int cg0 = (cc << 4) + cq * 4;
            float4 av = *(const float4*)&W5[(size_t)(ob + r) * 512 + cg0];
            float4 bv = *(const float4*)&cb[(size_t)(nb + r) * 512 + cg0];
            int cb_ = cq * 4;
            *(ull*)&Ad[(cb_ + 0) * 260 + 2 * r] = bcast2(av.x);
            *(ull*)&Ad[(cb_ + 1) * 260 + 2 * r] = bcast2(av.y);
            *(ull*)&Ad[(cb_ + 2) * 260 + 2 * r] = bcast2(av.z);
            *(ull*)&Ad[(cb_ + 3) * 260 + 2 * r] = bcast2(av.w);
            Bs_[(cb_ + 0) * 132 + r] = bv.x;
            Bs_[(cb_ + 1) * 132 + r] = bv.y;
            Bs_[(cb_ + 2) * 132 + r] = bv.z;
            Bs_[(cb_ + 3) * 132 + r] = bv.w;
        }
        __syncthreads();
#pragma unroll
        for (int c = 0; c < 16; c++) {
            const float4* arow = (const float4*)&Ad[c * 260 + ty * 16];
            const float4* brow = (const float4*)&Bs_[c * 132 + tx * 8];
            float4 bq0 = brow[0];
            float4 bq1 = brow[1];
            ull b0 = *(ull*)&bq0.x, b1 = *(ull*)&bq0.z;
            ull b2 = *(ull*)&bq1.x, b3 = *(ull*)&bq1.z;
#pragma unroll
            for (int iq = 0; iq < 4; iq++) {
                float4 aq = arow[iq];
                ull a0 = *(ull*)&aq.x;
                ull a1 = *(ull*)&aq.z;
                int i0 = 2 * iq, i1 = 2 * iq + 1;
                acc[i0][0] = ffma2(a0, b0, acc[i0][0]);
                acc[i0][1] = ffma2(a0, b1, acc[i0][1]);
                acc[i0][2] = ffma2(a0, b2, acc[i0][2]);
                acc[i0][3] = ffma2(a0, b3, acc[i0][3]);
                acc[i1][0] = ffma2(a1, b0, acc[i1][0]);
                acc[i1][1] = ffma2(a1, b1, acc[i1][1]);
                acc[i1][2] = ffma2(a1, b2, acc[i1][2]);
                acc[i1][3] = ffma2(a1, b3, acc[i1][3]);
            }
        }
        __syncthreads();
    }

#pragma unroll
    for (int i = 0; i < 8; i++) {
        float v[8];
#pragma unroll
        for (int j = 0; j < 4; j++) unpack2(acc[i][j], v[2 * j], v[2 * j + 1]);
        float mx = v[0], mn = v[0], s = v[0], q = v[0] * v[0];
#pragma unroll
        for (int j = 1; j < 8; j++) {
            mx = fmaxf(mx, v[j]);
            mn = fminf(mn, v[j]);
            s += v[j];
            q = fmaf(v[j], v[j], q);
        }
#pragma unroll
        for (int st = 8; st; st >>= 1) {
            mx = fmaxf(mx, __shfl_xor_sync(0xffffffffu, mx, st));
            mn = fminf(mn, __shfl_xor_sync(0xffffffffu, mn, st));
            s += __shfl_xor_sync(0xffffffffu, s, st);
            q += __shfl_xor_sync(0xffffffffu, q, st);
        }
        if (tx == 0) {
            int o = ob + ty * 8 + i;
            g_pmax[((size_t)b * O5 + o) * 8 + blockIdx.y] = mx;
            g_pmin[((size_t)b * O5 + o) * 8 + blockIdx.y] = mn;
            atomicAdd(&g_sum[o], s);
            atomicAdd(&g_sq[o], q);
        }
    }

    __syncthreads();
    __threadfence();
    __shared__ int isLast;
    if (tid == 0) isLast = (atomicAdd(&g_cnt, 1) == 511);
    __syncthreads();
    if (isLast) {
        volatile float* vs = g_sum;
        volatile float* vq = g_sq;
        for (int t = tid; t < BB * O5; t += 256) {
            int bb2 = t / O5, o = t % O5;
            float m = vs[o] / 8192.f;
            float var = vq[o] / 8192.f - m * m;
            float sc = g5[o] * rsqrtf(var + 1e-5f);
            float bi = b5[o] - m * sc;
            volatile float* pm = (sc >= 0.f) ? g_pmax : g_pmin;
            size_t base = ((size_t)bb2 * O5 + o) * 8;
            float sel = pm[base];
            if (sc >= 0.f) {
                for (int i = 1; i < 8; i++) sel = fmaxf(sel, pm[base + i]);
            } else {
                for (int i = 1; i < 8; i++) sel = fminf(sel, pm[base + i]);
            }
            float y = fmaf(sc, sel, bi);
            out[t] = (y >= 0.f) ? y : 0.2f * y;
        }
        if (tid == 0) g_cnt = 0;
    }
}

extern "C" void kernel_launch(void* const* d_in, const int* in_sizes, int n_in,
                              void* d_out, int out_size) {
    const float* x  = (const float*)d_in[0];
    const float* Wl[4] = {(const float*)d_in[1], (const float*)d_in[4],
                          (const float*)d_in[7], (const float*)d_in[10]};
    const float* gl[4] = {(const float*)d_in[2], (const float*)d_in[5],
                          (const float*)d_in[8], (const float*)d_in[11]};
    const float* bl[4] = {(const float*)d_in[3], (const float*)d_in[6],
                          (const float*)d_in[9], (const float*)d_in[12]};
    const float* W5 = (const float*)d_in[13];
    const float* g5 = (const float*)d_in[14];
    const float* b5 = (const float*)d_in[15];
    float* out = (float*)d_out;

    prep0<<<210, 256>>>(x, Wl[0], Wl[1], Wl[2], Wl[3]);

    const int srcA[4]  = {0, 1, 1, 1};
    const int offA[4]  = {0, 0, 64, 128};
    const int CA[4]    = {3, 64, 64, 128};
    const int CPA[4]   = {4, 64, 64, 128};
    const int OA[4]    = {64, 64, 128, 256};
    const int coffA[4] = {0, 64, 128, 256};
    const int woffA[4] = {0, 256, 4352, 12544};

    for (int L = 0; L < 4; L++) {
        int src = srcA[L], off = offA[L], C = CA[L], CP = CPA[L], O = OA[L];
        int coff = coffA[L], woff = woffA[L];
        int stride = src ? CAT : 4;
        int och = O / 64;
        kd_kernel<<<dim3(36, 1, BB), 256>>>(src, off, stride, C);
        tk2_kernel<<<1024 + 512 * och, 256>>>(src, off, stride, C, CP, O, och, woff);
        k3_kernel<<<dim3(64, BB), 256>>>(gl[L], bl[L], O, coff, (L < 3) ? 1 : 0);
    }

    f1_kernel<<<dim3(8, 8, BB), 256>>>(W5, g5, b5, out);
}